// round 1
// baseline (speedup 1.0000x reference)
#include <cuda_runtime.h>
#include <math.h>

// Problem constants
#define CB 32768   // batch
#define CD 256     // d_model (= H = O)
#define CE 8       // experts
constexpr int TM   = 64;    // token rows per tile
constexpr int APAD = 260;   // padded row stride (floats) for A tile in smem
constexpr int KC   = 32;    // k-chunk for W staging
constexpr int NT   = 256;   // threads per block

// Routing state (graph-capturable scratch: __device__ globals, no allocs)
__device__ int   g_counts[CE];
__device__ int   g_rtok[CE * CB];
__device__ float g_rw  [CE * CB];

// ---------------------------------------------------------------------------
// Zero output + routing counters (runs first every replay)
// ---------------------------------------------------------------------------
__global__ void zero_kernel(float* __restrict__ out, int n4)
{
    int i = blockIdx.x * blockDim.x + threadIdx.x;
    if (i < n4) {
        float4 z = make_float4(0.f, 0.f, 0.f, 0.f);
        reinterpret_cast<float4*>(out)[i] = z;
    }
    if (blockIdx.x == 0 && threadIdx.x < CE) g_counts[threadIdx.x] = 0;
}

// ---------------------------------------------------------------------------
// 64x256 += 64x256 * 256x256 GEMM (A in smem row-major APAD, W streamed in
// KC-row chunks). Thread (ty,tx): rows ty*4..+3, cols {64*jj + 4*tx + m}.
// Column mapping 4*tx+64*jj keeps all smem loads conflict-free.
// Ends with __syncthreads() so the caller may overwrite As.
// ---------------------------------------------------------------------------
__device__ __forceinline__ void gemm_tile(const float* __restrict__ W,
                                          const float* __restrict__ As,
                                          float* __restrict__ Ws,
                                          float (&acc)[4][16],
                                          int tx, int ty, int tid)
{
#pragma unroll
    for (int i = 0; i < 4; i++)
#pragma unroll
        for (int j = 0; j < 16; j++) acc[i][j] = 0.f;

    for (int kc = 0; kc < 256; kc += KC) {
        __syncthreads();
        // stage W[kc:kc+KC][0:256] -> Ws  (KC*256 floats = 2048 float4)
#pragma unroll
        for (int l = 0; l < (KC * 256 / 4) / NT; l++) {
            int idx = l * NT + tid;
            int kk  = idx >> 6;
            int c4  = idx & 63;
            reinterpret_cast<float4*>(Ws)[idx] =
                reinterpret_cast<const float4*>(W + (size_t)(kc + kk) * 256)[c4];
        }
        __syncthreads();

        const float* a0p = As + (ty * 4) * APAD + kc;
#pragma unroll 8
        for (int kk = 0; kk < KC; kk++) {
            float a0 = a0p[kk];
            float a1 = a0p[APAD + kk];
            float a2 = a0p[2 * APAD + kk];
            float a3 = a0p[3 * APAD + kk];
#pragma unroll
            for (int jj = 0; jj < 4; jj++) {
                float4 b = *reinterpret_cast<const float4*>(
                    Ws + kk * 256 + jj * 64 + tx * 4);
                acc[0][jj*4+0] += a0 * b.x; acc[0][jj*4+1] += a0 * b.y;
                acc[0][jj*4+2] += a0 * b.z; acc[0][jj*4+3] += a0 * b.w;
                acc[1][jj*4+0] += a1 * b.x; acc[1][jj*4+1] += a1 * b.y;
                acc[1][jj*4+2] += a1 * b.z; acc[1][jj*4+3] += a1 * b.w;
                acc[2][jj*4+0] += a2 * b.x; acc[2][jj*4+1] += a2 * b.y;
                acc[2][jj*4+2] += a2 * b.z; acc[2][jj*4+3] += a2 * b.w;
                acc[3][jj*4+0] += a3 * b.x; acc[3][jj*4+1] += a3 * b.y;
                acc[3][jj*4+2] += a3 * b.z; acc[3][jj*4+3] += a3 * b.w;
            }
        }
    }
    __syncthreads();   // all reads of As complete -> caller may overwrite
}

// ---------------------------------------------------------------------------
// bias add + LayerNorm + ReLU, write result back into As (A operand for the
// next GEMM). Row stats reduced across the 16 tx-lanes via shfl butterflies.
// ---------------------------------------------------------------------------
__device__ __forceinline__ void ln_relu_store(float (&acc)[4][16],
                                              const float* __restrict__ bias,
                                              const float* __restrict__ gamma,
                                              const float* __restrict__ beta,
                                              float* __restrict__ As,
                                              int tx, int ty)
{
    float s1[4] = {0.f, 0.f, 0.f, 0.f};
    float s2[4] = {0.f, 0.f, 0.f, 0.f};
#pragma unroll
    for (int jj = 0; jj < 4; jj++)
#pragma unroll
        for (int m = 0; m < 4; m++) {
            int c = jj * 64 + tx * 4 + m;
            float bv = __ldg(&bias[c]);
#pragma unroll
            for (int i = 0; i < 4; i++) {
                float v = acc[i][jj*4+m] + bv;
                acc[i][jj*4+m] = v;
                s1[i] += v;
                s2[i] += v * v;
            }
        }
#pragma unroll
    for (int off = 8; off > 0; off >>= 1)
#pragma unroll
        for (int i = 0; i < 4; i++) {
            s1[i] += __shfl_xor_sync(0xffffffffu, s1[i], off);
            s2[i] += __shfl_xor_sync(0xffffffffu, s2[i], off);
        }
    float mean[4], rstd[4];
#pragma unroll
    for (int i = 0; i < 4; i++) {
        mean[i] = s1[i] * (1.f / 256.f);
        float var = s2[i] * (1.f / 256.f) - mean[i] * mean[i];
        rstd[i] = rsqrtf(var + 1e-5f);
    }
#pragma unroll
    for (int jj = 0; jj < 4; jj++) {
        float gv[4], bev[4];
#pragma unroll
        for (int m = 0; m < 4; m++) {
            int c = jj * 64 + tx * 4 + m;
            gv[m]  = __ldg(&gamma[c]);
            bev[m] = __ldg(&beta[c]);
        }
#pragma unroll
        for (int i = 0; i < 4; i++) {
            float4 hv;
            hv.x = fmaxf((acc[i][jj*4+0] - mean[i]) * rstd[i] * gv[0] + bev[0], 0.f);
            hv.y = fmaxf((acc[i][jj*4+1] - mean[i]) * rstd[i] * gv[1] + bev[1], 0.f);
            hv.z = fmaxf((acc[i][jj*4+2] - mean[i]) * rstd[i] * gv[2] + bev[2], 0.f);
            hv.w = fmaxf((acc[i][jj*4+3] - mean[i]) * rstd[i] * gv[3] + bev[3], 0.f);
            *reinterpret_cast<float4*>(
                &As[(ty * 4 + i) * APAD + jj * 64 + tx * 4]) = hv;
        }
    }
}

// ---------------------------------------------------------------------------
// Gating: h = relu(x@gw1 + gb1); logits = h@gw2 + gb2; top-2; normalized
// weights; append (token, weight) to per-expert routing lists.
// ---------------------------------------------------------------------------
__global__ void __launch_bounds__(NT, 2)
gating_kernel(const float* __restrict__ x,
              const float* __restrict__ gw1, const float* __restrict__ gb1,
              const float* __restrict__ gw2, const float* __restrict__ gb2)
{
    extern __shared__ float sm[];
    float* As   = sm;                       // TM*APAD
    float* Ws   = As + TM * APAD;           // KC*256
    float* gw2s = Ws + KC * 256;            // 8*256 (transposed [e][c])
    __shared__ float logitsS[TM][CE];

    int tid = threadIdx.x;
    int tx  = tid & 15;
    int ty  = tid >> 4;
    int t0  = blockIdx.x * TM;

    // stage gw2 transposed: gw2s[e*256 + c] = gw2[c*8 + e]
    for (int idx = tid; idx < 256 * CE; idx += NT) {
        int c = idx >> 3, e = idx & 7;
        gw2s[e * 256 + c] = gw2[idx];
    }
    // gather contiguous x rows
    for (int idx = tid; idx < TM * 256; idx += NT) {
        int r = idx >> 8, k = idx & 255;
        As[r * APAD + k] = x[(size_t)(t0 + r) * 256 + k];
    }

    float acc[4][16];
    gemm_tile(gw1, As, Ws, acc, tx, ty, tid);

    // + gb1, relu
#pragma unroll
    for (int jj = 0; jj < 4; jj++)
#pragma unroll
        for (int m = 0; m < 4; m++) {
            int c = jj * 64 + tx * 4 + m;
            float bv = __ldg(&gb1[c]);
#pragma unroll
            for (int i = 0; i < 4; i++)
                acc[i][jj*4+m] = fmaxf(acc[i][jj*4+m] + bv, 0.f);
        }

    // logits: per expert, partial over this thread's 16 cols, shfl-reduce
    for (int e = 0; e < CE; e++) {
        float l0 = 0.f, l1 = 0.f, l2 = 0.f, l3 = 0.f;
#pragma unroll
        for (int jj = 0; jj < 4; jj++)
#pragma unroll
            for (int m = 0; m < 4; m++) {
                int c = jj * 64 + tx * 4 + m;
                float g = gw2s[e * 256 + c];
                l0 += acc[0][jj*4+m] * g;
                l1 += acc[1][jj*4+m] * g;
                l2 += acc[2][jj*4+m] * g;
                l3 += acc[3][jj*4+m] * g;
            }
#pragma unroll
        for (int off = 8; off > 0; off >>= 1) {
            l0 += __shfl_xor_sync(0xffffffffu, l0, off);
            l1 += __shfl_xor_sync(0xffffffffu, l1, off);
            l2 += __shfl_xor_sync(0xffffffffu, l2, off);
            l3 += __shfl_xor_sync(0xffffffffu, l3, off);
        }
        if (tx == 0) {
            float gb = __ldg(&gb2[e]);
            logitsS[ty * 4 + 0][e] = l0 + gb;
            logitsS[ty * 4 + 1][e] = l1 + gb;
            logitsS[ty * 4 + 2][e] = l2 + gb;
            logitsS[ty * 4 + 3][e] = l3 + gb;
        }
    }
    __syncthreads();

    if (tid < TM) {
        float l[CE];
#pragma unroll
        for (int e = 0; e < CE; e++) l[e] = logitsS[tid][e];
        int i0 = 0;
#pragma unroll
        for (int e = 1; e < CE; e++) if (l[e] > l[i0]) i0 = e;
        int i1 = (i0 == 0) ? 1 : 0;
#pragma unroll
        for (int e = 0; e < CE; e++)
            if (e != i0 && l[e] > l[i1]) i1 = e;
        // softmax top-2 normalized weights: w0 = p0/(p0+p1)
        float w0 = 1.f / (1.f + expf(l[i1] - l[i0]));
        int tok = t0 + tid;
        int p0 = atomicAdd(&g_counts[i0], 1);
        g_rtok[i0 * CB + p0] = tok;
        g_rw  [i0 * CB + p0] = w0;
        int p1 = atomicAdd(&g_counts[i1], 1);
        g_rtok[i1 * CB + p1] = tok;
        g_rw  [i1 * CB + p1] = 1.f - w0;
    }
}

// ---------------------------------------------------------------------------
// Expert kernel: per (expert, 64-token tile of that expert's routed list),
// fully fused  X -> GEMM1+LN+ReLU -> GEMM2+LN+ReLU -> GEMM3 -> weighted
// atomicAdd into output. Only routed tokens are computed (4x FLOP cut).
// ---------------------------------------------------------------------------
__global__ void __launch_bounds__(NT, 2)
expert_kernel(const float* __restrict__ x,
              const float* __restrict__ w1, const float* __restrict__ b1,
              const float* __restrict__ g1, const float* __restrict__ be1,
              const float* __restrict__ w2, const float* __restrict__ b2,
              const float* __restrict__ g2, const float* __restrict__ be2,
              const float* __restrict__ w3, const float* __restrict__ b3,
              float* __restrict__ out)
{
    int e = blockIdx.y;
    int count = g_counts[e];
    int t0 = blockIdx.x * TM;
    if (t0 >= count) return;
    int mrows = count - t0;
    if (mrows > TM) mrows = TM;

    extern __shared__ float sm[];
    float* As = sm;               // TM*APAD
    float* Ws = As + TM * APAD;   // KC*256
    __shared__ int   tokS[TM];
    __shared__ float wS[TM];

    int tid = threadIdx.x;
    int tx  = tid & 15;
    int ty  = tid >> 4;

    if (tid < TM) {
        int idx = t0 + tid;
        tokS[tid] = (tid < mrows) ? g_rtok[e * CB + idx] : 0;
        wS[tid]   = (tid < mrows) ? g_rw[e * CB + idx]   : 0.f;
    }
    __syncthreads();

    // gather X rows for this tile (zero-fill tail rows to keep LN finite)
    for (int idx = tid; idx < TM * 256; idx += NT) {
        int r = idx >> 8, k = idx & 255;
        As[r * APAD + k] = (r < mrows) ? x[(size_t)tokS[r] * 256 + k] : 0.f;
    }

    const size_t eW = (size_t)e * 256 * 256;
    const int    eV = e * 256;
    float acc[4][16];

    gemm_tile(w1 + eW, As, Ws, acc, tx, ty, tid);
    ln_relu_store(acc, b1 + eV, g1 + eV, be1 + eV, As, tx, ty);

    gemm_tile(w2 + eW, As, Ws, acc, tx, ty, tid);
    ln_relu_store(acc, b2 + eV, g2 + eV, be2 + eV, As, tx, ty);

    gemm_tile(w3 + eW, As, Ws, acc, tx, ty, tid);

    // + b3, scale by routing weight, accumulate into output
    const float* b3v = b3 + eV;
#pragma unroll
    for (int i = 0; i < 4; i++) {
        int r = ty * 4 + i;
        if (r < mrows) {
            float w = wS[r];
            float* orow = out + (size_t)tokS[r] * 256;
#pragma unroll
            for (int jj = 0; jj < 4; jj++)
#pragma unroll
                for (int mm = 0; mm < 4; mm++) {
                    int c = jj * 64 + tx * 4 + mm;
                    atomicAdd(&orow[c], w * (acc[i][jj*4+mm] + __ldg(&b3v[c])));
                }
        }
    }
}

// ---------------------------------------------------------------------------
// Launch
// ---------------------------------------------------------------------------
extern "C" void kernel_launch(void* const* d_in, const int* in_sizes, int n_in,
                              void* d_out, int out_size)
{
    const float* x   = (const float*)d_in[0];
    const float* gw1 = (const float*)d_in[1];
    const float* gb1 = (const float*)d_in[2];
    const float* gw2 = (const float*)d_in[3];
    const float* gb2 = (const float*)d_in[4];
    const float* w1  = (const float*)d_in[5];
    const float* b1  = (const float*)d_in[6];
    const float* g1  = (const float*)d_in[7];
    const float* be1 = (const float*)d_in[8];
    const float* w2  = (const float*)d_in[9];
    const float* b2  = (const float*)d_in[10];
    const float* g2  = (const float*)d_in[11];
    const float* be2 = (const float*)d_in[12];
    const float* w3  = (const float*)d_in[13];
    const float* b3  = (const float*)d_in[14];
    float* out = (float*)d_out;

    const int smem_gemm   = (TM * APAD + KC * 256) * (int)sizeof(float);
    const int smem_gating = smem_gemm + 256 * CE * (int)sizeof(float);

    cudaFuncSetAttribute(gating_kernel,
                         cudaFuncAttributeMaxDynamicSharedMemorySize, smem_gating);
    cudaFuncSetAttribute(expert_kernel,
                         cudaFuncAttributeMaxDynamicSharedMemorySize, smem_gemm);

    int n4 = out_size / 4;
    zero_kernel<<<(n4 + NT - 1) / NT, NT>>>(out, n4);

    gating_kernel<<<CB / TM, NT, smem_gating>>>(x, gw1, gb1, gw2, gb2);

    dim3 egrid(CB / TM, CE);
    expert_kernel<<<egrid, NT, smem_gemm>>>(x, w1, b1, g1, be1,
                                            w2, b2, g2, be2, w3, b3, out);
}

// round 5
// speedup vs baseline: 1.2964x; 1.2964x over previous
#include <cuda_runtime.h>
#include <cstdint>
#include <math.h>

#define CB 32768
#define CE 8
constexpr int NT   = 256;     // threads per block (8 warps)
constexpr int BM   = 64;      // token rows per tile
constexpr int AP   = 260;     // A row stride (floats), conflict-free
constexpr int SLAB = 65536;   // floats per 256x256 slab
constexpr int NSLAB = 25;
constexpr int LO_OFF = NSLAB * SLAB;   // lo-plane offset within g_wfrag

// ---------------------------------------------------------------------------
// Device scratch (static, graph-capturable)
// ---------------------------------------------------------------------------
__device__ int   g_counts[CE];
__device__ int   g_nfix;
__device__ int   g_fixlist[CB];
__device__ int   g_sel[CB];            // i0 | (i1<<8)
__device__ float g_w0[CB];
__device__ int   g_rtok[CE * CB];
__device__ float g_rw[CE * CB];
__device__ int   g_rdst[CE * CB];
__device__ float g_wfrag[2 * NSLAB * SLAB];   // [hi slabs][lo slabs], frag order
__device__ float g_eout[2 * CB * 256];

// ---------------------------------------------------------------------------
__device__ __forceinline__ uint32_t f2tf32(float f) {
    uint32_t u; asm("cvt.rna.tf32.f32 %0, %1;" : "=r"(u) : "f"(f)); return u;
}
__device__ __forceinline__ float rtf(float f) { return __uint_as_float(f2tf32(f)); }

__device__ __forceinline__ void mma_tf32(float (&c)[4], const uint32_t (&a)[4],
                                         const uint32_t (&b)[2]) {
    asm volatile(
        "mma.sync.aligned.m16n8k8.row.col.f32.tf32.tf32.f32 "
        "{%0,%1,%2,%3}, {%4,%5,%6,%7}, {%8,%9}, {%0,%1,%2,%3};"
        : "+f"(c[0]), "+f"(c[1]), "+f"(c[2]), "+f"(c[3])
        : "r"(a[0]), "r"(a[1]), "r"(a[2]), "r"(a[3]), "r"(b[0]), "r"(b[1]));
}

// Stage one K=16 chunk: hi plane (4096 floats) + lo plane into Bs.
__device__ __forceinline__ void prefetch_chunk(const float* __restrict__ Wg, int cc,
                                               float* bs, int tid) {
    unsigned dst = (unsigned)__cvta_generic_to_shared(bs);
    const float* hi = Wg + cc * 4096;
    const float* lo = Wg + LO_OFF + cc * 4096;
#pragma unroll
    for (int i = 0; i < 4; i++) {
        int idx = i * NT + tid;
        asm volatile("cp.async.cg.shared.global [%0], [%1], 16;"
                     :: "r"(dst + idx * 16), "l"(hi + idx * 4));
    }
#pragma unroll
    for (int i = 0; i < 4; i++) {
        int idx = i * NT + tid;
        asm volatile("cp.async.cg.shared.global [%0], [%1], 16;"
                     :: "r"(dst + 16384 + idx * 16), "l"(lo + idx * 4));
    }
    asm volatile("cp.async.commit_group;");
}

// ---------------------------------------------------------------------------
// 64x256x256 GEMM, 3xTF32 split (a_hi*b_hi + a_hi*b_lo + a_lo*b_hi).
// A: two smem planes [64][AP] (tf32-rounded hi, lo). B: fragment-packed slabs.
// Fragment layout (verified in R4): per chunk cc (K=16), step s (k8),
// n-tile nt: off = cc*4096 + (s*32+nt)*64 + lane*2 + r;
//   k = cc*16 + s*8 + (lane&3) + r*4,  n = nt*8 + (lane>>2).
// ---------------------------------------------------------------------------
__device__ __forceinline__ void gemm_core(const float* __restrict__ Wg,
                                          const float* __restrict__ Ah,
                                          const float* __restrict__ Al,
                                          float* BsBase, float (&c)[2][8][4],
                                          int wm, int wn, int lane, int tid)
{
    int g  = lane >> 2;
    int tg = lane & 3;
#pragma unroll
    for (int m = 0; m < 2; m++)
#pragma unroll
        for (int t = 0; t < 8; t++)
#pragma unroll
            for (int k = 0; k < 4; k++) c[m][t][k] = 0.f;

    prefetch_chunk(Wg, 0, BsBase, tid);

    for (int cc = 0; cc < 16; cc++) {
        if (cc < 15) {
            prefetch_chunk(Wg, cc + 1, BsBase + ((cc + 1) & 1) * 8192, tid);
            asm volatile("cp.async.wait_group 1;" ::: "memory");
        } else {
            asm volatile("cp.async.wait_group 0;" ::: "memory");
        }
        __syncthreads();

        const float* bh = BsBase + (cc & 1) * 8192;
        const float* bl = bh + 4096;
        const float* aBh = Ah + (wm * 32 + g) * AP + cc * 16 + tg;
        const float* aBl = Al + (wm * 32 + g) * AP + cc * 16 + tg;
#pragma unroll
        for (int s = 0; s < 2; s++) {
            uint32_t ah[2][4], al[2][4];
#pragma unroll
            for (int m = 0; m < 2; m++) {
                const float* p = aBh + m * 16 * AP + s * 8;
                ah[m][0] = __float_as_uint(p[0]);
                ah[m][1] = __float_as_uint(p[8 * AP]);
                ah[m][2] = __float_as_uint(p[4]);
                ah[m][3] = __float_as_uint(p[8 * AP + 4]);
                const float* q = aBl + m * 16 * AP + s * 8;
                al[m][0] = __float_as_uint(q[0]);
                al[m][1] = __float_as_uint(q[8 * AP]);
                al[m][2] = __float_as_uint(q[4]);
                al[m][3] = __float_as_uint(q[8 * AP + 4]);
            }
            const float* bph = bh + (s * 32 + wn * 8) * 64 + lane * 2;
            const float* bpl = bl + (s * 32 + wn * 8) * 64 + lane * 2;
#pragma unroll
            for (int t = 0; t < 8; t++) {
                float2 vh = *reinterpret_cast<const float2*>(bph + t * 64);
                float2 vl = *reinterpret_cast<const float2*>(bpl + t * 64);
                uint32_t bhf[2] = { __float_as_uint(vh.x), __float_as_uint(vh.y) };
                uint32_t blf[2] = { __float_as_uint(vl.x), __float_as_uint(vl.y) };
#pragma unroll
                for (int m = 0; m < 2; m++) {
                    mma_tf32(c[m][t], ah[m], bhf);
                    mma_tf32(c[m][t], ah[m], blf);
                    mma_tf32(c[m][t], al[m], bhf);
                }
            }
        }
        __syncthreads();
    }
}

// ---------------------------------------------------------------------------
// prep: zero counters; pack 25 slabs into hi/lo tf32 fragment planes.
// grid (256, 25) x 256.
// ---------------------------------------------------------------------------
__global__ void prep_kernel(const float* __restrict__ gw1,
                            const float* __restrict__ w1,
                            const float* __restrict__ w2,
                            const float* __restrict__ w3)
{
    int tid = threadIdx.x;
    if (blockIdx.x == 0 && blockIdx.y == 0) {
        if (tid < CE) g_counts[tid] = 0;
        if (tid == CE) g_nfix = 0;
    }
    int slab = blockIdx.y;
    const float* src;
    if (slab == 0) src = gw1;
    else {
        int e = (slab - 1) / 3, l = (slab - 1) % 3;
        src = (l == 0 ? w1 : (l == 1 ? w2 : w3)) + (size_t)e * SLAB;
    }
    int idx = blockIdx.x * NT + tid;
    int r    = idx & 1;
    int lane = (idx >> 1) & 31;
    int nt   = (idx >> 6) & 31;
    int s    = (idx >> 11) & 1;
    int cc   = idx >> 12;
    int k = cc * 16 + s * 8 + (lane & 3) + r * 4;
    int n = nt * 8 + (lane >> 2);
    float w  = src[(size_t)k * 256 + n];
    float hi = rtf(w);
    float lo = rtf(w - hi);
    g_wfrag[(size_t)slab * SLAB + idx]          = hi;
    g_wfrag[(size_t)LO_OFF + slab * SLAB + idx] = lo;
}

// ---------------------------------------------------------------------------
// Gating: 3xTF32 GEMM1 -> relu(+gb1) -> fp32 logits vs gw2 -> top-2 ->
// per-token selection + w0; near-tie tokens flagged for exact fixup.
// ---------------------------------------------------------------------------
__global__ void __launch_bounds__(NT, 1)
gating_kernel(const float* __restrict__ x,
              const float* __restrict__ gb1,
              const float* __restrict__ gw2,
              const float* __restrict__ gb2)
{
    extern __shared__ float sm[];
    float* Ah = sm;                   // 64*AP
    float* Al = sm + BM * AP;         // 64*AP
    float* Bs = sm + 2 * BM * AP;     // 2*8192

    __shared__ float gw2s[256 * 8];
    __shared__ float gb1s[256];
    __shared__ float lgS[4][BM][8];

    int tid  = threadIdx.x;
    int wid  = tid >> 5;
    int lane = tid & 31;
    int wm = wid >> 2, wn = wid & 3;
    int g = lane >> 2, tg = lane & 3;
    int t0 = blockIdx.x * BM;

    for (int i = tid; i < 2048; i += NT) gw2s[i] = gw2[i];
    if (tid < 256) gb1s[tid] = gb1[tid];

    // A = x rows, hi/lo tf32 split
    const float4* x4 = reinterpret_cast<const float4*>(x);
    for (int i = tid; i < BM * 64; i += NT) {
        int rr = i >> 6, c4 = i & 63;
        float4 v = __ldg(&x4[(size_t)(t0 + rr) * 64 + c4]);
        float4 h, l;
        h.x = rtf(v.x); l.x = rtf(v.x - h.x);
        h.y = rtf(v.y); l.y = rtf(v.y - h.y);
        h.z = rtf(v.z); l.z = rtf(v.z - h.z);
        h.w = rtf(v.w); l.w = rtf(v.w - h.w);
        *reinterpret_cast<float4*>(Ah + rr * AP + c4 * 4) = h;
        *reinterpret_cast<float4*>(Al + rr * AP + c4 * 4) = l;
    }
    __syncthreads();

    float c[2][8][4];
    gemm_core(g_wfrag, Ah, Al, Bs, c, wm, wn, lane, tid);

    // logits partials (fp32)
    float lg[2][2][8];
#pragma unroll
    for (int m = 0; m < 2; m++)
#pragma unroll
        for (int h = 0; h < 2; h++)
#pragma unroll
            for (int e = 0; e < 8; e++) lg[m][h][e] = 0.f;

#pragma unroll
    for (int m = 0; m < 2; m++)
#pragma unroll
        for (int t = 0; t < 8; t++) {
            int colb = wn * 64 + t * 8 + tg * 2;
#pragma unroll
            for (int h = 0; h < 2; h++)
#pragma unroll
                for (int q = 0; q < 2; q++) {
                    int col = colb + q;
                    float hv = fmaxf(c[m][t][h * 2 + q] + gb1s[col], 0.f);
                    const float4* gp = reinterpret_cast<const float4*>(gw2s + col * 8);
                    float4 p0 = gp[0], p1 = gp[1];
                    lg[m][h][0] += hv * p0.x; lg[m][h][1] += hv * p0.y;
                    lg[m][h][2] += hv * p0.z; lg[m][h][3] += hv * p0.w;
                    lg[m][h][4] += hv * p1.x; lg[m][h][5] += hv * p1.y;
                    lg[m][h][6] += hv * p1.z; lg[m][h][7] += hv * p1.w;
                }
        }
#pragma unroll
    for (int off = 1; off <= 2; off <<= 1)
#pragma unroll
        for (int m = 0; m < 2; m++)
#pragma unroll
            for (int h = 0; h < 2; h++)
#pragma unroll
                for (int e = 0; e < 8; e++)
                    lg[m][h][e] += __shfl_xor_sync(0xffffffffu, lg[m][h][e], off);
    if (tg == 0) {
#pragma unroll
        for (int m = 0; m < 2; m++)
#pragma unroll
            for (int h = 0; h < 2; h++) {
                int row = wm * 32 + m * 16 + g + h * 8;
#pragma unroll
                for (int e = 0; e < 8; e++) lgS[wn][row][e] = lg[m][h][e];
            }
    }
    __syncthreads();

    if (tid < BM) {
        float l[CE];
#pragma unroll
        for (int e = 0; e < CE; e++)
            l[e] = lgS[0][tid][e] + lgS[1][tid][e] + lgS[2][tid][e] + lgS[3][tid][e]
                 + __ldg(&gb2[e]);
        int i0 = 0;
#pragma unroll
        for (int e = 1; e < CE; e++) if (l[e] > l[i0]) i0 = e;
        int i1 = (i0 == 0) ? 1 : 0;
#pragma unroll
        for (int e = 0; e < CE; e++) if (e != i0 && l[e] > l[i1]) i1 = e;
        float l2v = -1e30f;
#pragma unroll
        for (int e = 0; e < CE; e++)
            if (e != i0 && e != i1 && l[e] > l2v) l2v = l[e];
        float w0 = 1.f / (1.f + expf(l[i1] - l[i0]));
        int tok = t0 + tid;
        g_sel[tok] = i0 | (i1 << 8);
        g_w0[tok]  = w0;
        if (l[i1] - l2v < 1e-4f) {           // near-tie: exact recompute later
            int p = atomicAdd(&g_nfix, 1);
            g_fixlist[p] = tok;
        }
    }
}

// ---------------------------------------------------------------------------
// Exact-fp32 gating recompute for flagged near-tie tokens.
// ---------------------------------------------------------------------------
__global__ void fixup_kernel(const float* __restrict__ x,
                             const float* __restrict__ gw1,
                             const float* __restrict__ gb1,
                             const float* __restrict__ gw2,
                             const float* __restrict__ gb2)
{
    __shared__ float hS[256];
    __shared__ float lg8[CE];
    int nf = g_nfix;
    int tid = threadIdx.x;
    for (int i = blockIdx.x; i < nf; i += gridDim.x) {
        int t = g_fixlist[i];
        const float* xr = x + (size_t)t * 256;
        float acc = 0.f;
        for (int k = 0; k < 256; k++)
            acc = fmaf(__ldg(&xr[k]), __ldg(&gw1[(size_t)k * 256 + tid]), acc);
        hS[tid] = fmaxf(acc + __ldg(&gb1[tid]), 0.f);
        __syncthreads();
        int wid = tid >> 5, lane = tid & 31;
        float s = 0.f;
        for (int j = lane; j < 256; j += 32) s += hS[j] * __ldg(&gw2[j * 8 + wid]);
#pragma unroll
        for (int o = 16; o > 0; o >>= 1) s += __shfl_xor_sync(0xffffffffu, s, o);
        if (lane == 0) lg8[wid] = s + __ldg(&gb2[wid]);
        __syncthreads();
        if (tid == 0) {
            float l[CE];
#pragma unroll
            for (int e = 0; e < CE; e++) l[e] = lg8[e];
            int i0 = 0;
#pragma unroll
            for (int e = 1; e < CE; e++) if (l[e] > l[i0]) i0 = e;
            int i1 = (i0 == 0) ? 1 : 0;
#pragma unroll
            for (int e = 0; e < CE; e++) if (e != i0 && l[e] > l[i1]) i1 = e;
            g_sel[t] = i0 | (i1 << 8);
            g_w0[t]  = 1.f / (1.f + expf(l[i1] - l[i0]));
        }
        __syncthreads();
    }
}

// ---------------------------------------------------------------------------
// Build per-expert routed lists (block-aggregated atomics).
// ---------------------------------------------------------------------------
__global__ void route_kernel()
{
    __shared__ int cnt[CE], baseI[CE];
    int tid = threadIdx.x;
    int t = blockIdx.x * NT + tid;
    if (tid < CE) cnt[tid] = 0;
    __syncthreads();
    int sel = g_sel[t];
    int e0 = sel & 255, e1 = sel >> 8;
    float w0 = g_w0[t];
    int p0 = atomicAdd(&cnt[e0], 1);
    int p1 = atomicAdd(&cnt[e1], 1);
    __syncthreads();
    if (tid < CE) baseI[tid] = atomicAdd(&g_counts[tid], cnt[tid]);
    __syncthreads();
    int q0 = e0 * CB + baseI[e0] + p0;
    g_rtok[q0] = t; g_rw[q0] = w0;        g_rdst[q0] = 2 * t;
    int q1 = e1 * CB + baseI[e1] + p1;
    g_rtok[q1] = t; g_rw[q1] = 1.f - w0;  g_rdst[q1] = 2 * t + 1;
}

// ---------------------------------------------------------------------------
// Expert kernel: fused 3-layer MLP on routed 64-token tiles (3xTF32 GEMMs);
// LN in registers; weighted rows to g_eout (no atomics).
// ---------------------------------------------------------------------------
__global__ void __launch_bounds__(NT, 1)
expert_kernel(const float* __restrict__ x,
              const float* __restrict__ b1, const float* __restrict__ g1,
              const float* __restrict__ be1,
              const float* __restrict__ b2, const float* __restrict__ g2,
              const float* __restrict__ be2,
              const float* __restrict__ b3)
{
    int e = blockIdx.y;
    int count = g_counts[e];
    int t0 = blockIdx.x * BM;
    if (t0 >= count) return;
    int mrows = min(BM, count - t0);

    extern __shared__ float sm[];
    float* Ah = sm;
    float* Al = sm + BM * AP;
    float* Bs = sm + 2 * BM * AP;

    __shared__ int   tokS[BM];
    __shared__ float wS[BM];
    __shared__ int   dstS[BM];
    __shared__ float biasS[256], gamS[256], betS[256];
    __shared__ float redS[4][BM][2];
    __shared__ float mrS[BM][2];

    int tid  = threadIdx.x;
    int wid  = tid >> 5;
    int lane = tid & 31;
    int wm = wid >> 2, wn = wid & 3;
    int g = lane >> 2, tg = lane & 3;

    if (tid < BM) {
        bool v = tid < mrows;
        int q = e * CB + t0 + tid;
        tokS[tid] = v ? g_rtok[q] : 0;
        wS[tid]   = v ? g_rw[q]   : 0.f;
        dstS[tid] = v ? g_rdst[q] : 0;
    }
    __syncthreads();

    // A = gathered x rows, hi/lo split
    const float4* x4 = reinterpret_cast<const float4*>(x);
    for (int i = tid; i < BM * 64; i += NT) {
        int rr = i >> 6, c4 = i & 63;
        float4 v = __ldg(&x4[(size_t)tokS[rr] * 64 + c4]);
        float4 h, l;
        h.x = rtf(v.x); l.x = rtf(v.x - h.x);
        h.y = rtf(v.y); l.y = rtf(v.y - h.y);
        h.z = rtf(v.z); l.z = rtf(v.z - h.z);
        h.w = rtf(v.w); l.w = rtf(v.w - h.w);
        *reinterpret_cast<float4*>(Ah + rr * AP + c4 * 4) = h;
        *reinterpret_cast<float4*>(Al + rr * AP + c4 * 4) = l;
    }

    float c[2][8][4];

    for (int l = 0; l < 3; l++) {
        if (tid < 256) {
            biasS[tid] = (l == 0 ? b1 : (l == 1 ? b2 : b3))[e * 256 + tid];
            if (l < 2) {
                gamS[tid] = (l == 0 ? g1 : g2)[e * 256 + tid];
                betS[tid] = (l == 0 ? be1 : be2)[e * 256 + tid];
            }
        }
        __syncthreads();

        gemm_core(g_wfrag + (size_t)(1 + e * 3 + l) * SLAB, Ah, Al, Bs,
                  c, wm, wn, lane, tid);

        if (l < 2) {
            float s1[2][2] = {{0.f, 0.f}, {0.f, 0.f}};
            float s2[2][2] = {{0.f, 0.f}, {0.f, 0.f}};
#pragma unroll
            for (int m = 0; m < 2; m++)
#pragma unroll
                for (int t = 0; t < 8; t++) {
                    int colb = wn * 64 + t * 8 + tg * 2;
#pragma unroll
                    for (int h = 0; h < 2; h++)
#pragma unroll
                        for (int q = 0; q < 2; q++) {
                            float v = c[m][t][h * 2 + q] + biasS[colb + q];
                            c[m][t][h * 2 + q] = v;
                            s1[m][h] += v; s2[m][h] += v * v;
                        }
                }
#pragma unroll
            for (int off = 1; off <= 2; off <<= 1)
#pragma unroll
                for (int m = 0; m < 2; m++)
#pragma unroll
                    for (int h = 0; h < 2; h++) {
                        s1[m][h] += __shfl_xor_sync(0xffffffffu, s1[m][h], off);
                        s2[m][h] += __shfl_xor_sync(0xffffffffu, s2[m][h], off);
                    }
            if (tg == 0) {
#pragma unroll
                for (int m = 0; m < 2; m++)
#pragma unroll
                    for (int h = 0; h < 2; h++) {
                        int row = wm * 32 + m * 16 + g + h * 8;
                        redS[wn][row][0] = s1[m][h];
                        redS[wn][row][1] = s2[m][h];
                    }
            }
            __syncthreads();
            if (tid < BM) {
                float a = redS[0][tid][0] + redS[1][tid][0] + redS[2][tid][0] + redS[3][tid][0];
                float b = redS[0][tid][1] + redS[1][tid][1] + redS[2][tid][1] + redS[3][tid][1];
                float mean = a * (1.f / 256.f);
                float var  = b * (1.f / 256.f) - mean * mean;
                mrS[tid][0] = mean;
                mrS[tid][1] = rsqrtf(var + 1e-5f);
            }
            __syncthreads();
#pragma unroll
            for (int m = 0; m < 2; m++)
#pragma unroll
                for (int h = 0; h < 2; h++) {
                    int row = wm * 32 + m * 16 + g + h * 8;
                    float mean = mrS[row][0], rs = mrS[row][1];
#pragma unroll
                    for (int t = 0; t < 8; t++) {
                        int colb = wn * 64 + t * 8 + tg * 2;
                        float h0 = fmaxf((c[m][t][h * 2 + 0] - mean) * rs * gamS[colb]
                                         + betS[colb], 0.f);
                        float h1 = fmaxf((c[m][t][h * 2 + 1] - mean) * rs * gamS[colb + 1]
                                         + betS[colb + 1], 0.f);
                        float hi0 = rtf(h0), lo0 = rtf(h0 - hi0);
                        float hi1 = rtf(h1), lo1 = rtf(h1 - hi1);
                        *reinterpret_cast<float2*>(Ah + row * AP + colb) = make_float2(hi0, hi1);
                        *reinterpret_cast<float2*>(Al + row * AP + colb) = make_float2(lo0, lo1);
                    }
                }
            __syncthreads();
        }
    }

    // final: +b3, gate weight, store rows to g_eout[dst]
#pragma unroll
    for (int m = 0; m < 2; m++)
#pragma unroll
        for (int h = 0; h < 2; h++) {
            int row = wm * 32 + m * 16 + g + h * 8;
            if (row < mrows) {
                float wgt = wS[row];
                float* orow = g_eout + (size_t)dstS[row] * 256;
#pragma unroll
                for (int t = 0; t < 8; t++) {
                    int colb = wn * 64 + t * 8 + tg * 2;
                    float2 v = make_float2(
                        wgt * (c[m][t][h * 2 + 0] + biasS[colb]),
                        wgt * (c[m][t][h * 2 + 1] + biasS[colb + 1]));
                    *reinterpret_cast<float2*>(orow + colb) = v;
                }
            }
        }
}

// ---------------------------------------------------------------------------
__global__ void combine_kernel(float* __restrict__ out)
{
    int i = blockIdx.x * blockDim.x + threadIdx.x;   // CB*64 float4s
    if (i >= CB * 64) return;
    int t = i >> 6, c4 = i & 63;
    const float4* e4 = reinterpret_cast<const float4*>(g_eout);
    float4 a = e4[(size_t)(2 * t) * 64 + c4];
    float4 b = e4[(size_t)(2 * t + 1) * 64 + c4];
    reinterpret_cast<float4*>(out)[i] =
        make_float4(a.x + b.x, a.y + b.y, a.z + b.z, a.w + b.w);
}

// ---------------------------------------------------------------------------
extern "C" void kernel_launch(void* const* d_in, const int* in_sizes, int n_in,
                              void* d_out, int out_size)
{
    const float* x   = (const float*)d_in[0];
    const float* gw1 = (const float*)d_in[1];
    const float* gb1 = (const float*)d_in[2];
    const float* gw2 = (const float*)d_in[3];
    const float* gb2 = (const float*)d_in[4];
    const float* w1  = (const float*)d_in[5];
    const float* b1  = (const float*)d_in[6];
    const float* g1  = (const float*)d_in[7];
    const float* be1 = (const float*)d_in[8];
    const float* w2  = (const float*)d_in[9];
    const float* b2  = (const float*)d_in[10];
    const float* g2  = (const float*)d_in[11];
    const float* be2 = (const float*)d_in[12];
    const float* w3  = (const float*)d_in[13];
    const float* b3  = (const float*)d_in[14];
    float* out = (float*)d_out;

    const int smem_bytes = (2 * BM * AP + 2 * 8192) * (int)sizeof(float);  // 198656

    cudaFuncSetAttribute(gating_kernel,
                         cudaFuncAttributeMaxDynamicSharedMemorySize, smem_bytes);
    cudaFuncSetAttribute(expert_kernel,
                         cudaFuncAttributeMaxDynamicSharedMemorySize, smem_bytes);

    prep_kernel<<<dim3(256, 25), NT>>>(gw1, w1, w2, w3);

    gating_kernel<<<CB / BM, NT, smem_bytes>>>(x, gb1, gw2, gb2);

    fixup_kernel<<<64, NT>>>(x, gw1, gb1, gw2, gb2);

    route_kernel<<<CB / NT, NT>>>();

    dim3 egrid(CB / BM, CE);
    expert_kernel<<<egrid, NT, smem_bytes>>>(x, b1, g1, be1, b2, g2, be2, b3);

    combine_kernel<<<(CB * 64 + NT - 1) / NT, NT>>>(out);
}

// round 6
// speedup vs baseline: 1.9582x; 1.5105x over previous
#include <cuda_runtime.h>
#include <cuda_fp16.h>
#include <cstdint>
#include <math.h>

#define CB 32768
#define CE 8
constexpr int NT   = 256;     // threads per block (8 warps)
constexpr int BM   = 64;      // token rows per tile
constexpr int APH  = 264;     // A row stride in fp16 units (conflict-free pad)
constexpr int SLABQ = 16384;  // uint4 per packed 256x256 slab
constexpr int CHQ   = 2048;   // uint4 per K=32 chunk
constexpr int NBUF  = 3;      // B buffers

// ---------------------------------------------------------------------------
// Device scratch (static, graph-capturable)
// ---------------------------------------------------------------------------
__device__ int   g_counts[CE];
__device__ int   g_nfix;
__device__ int   g_fixlist[CB];
__device__ int   g_sel[CB];            // i0 | (i1<<8)
__device__ float g_w0[CB];
__device__ int   g_rtok[CE * CB];
__device__ float g_rw[CE * CB];
__device__ int   g_rdst[CE * CB];
__device__ uint4 g_wpack[25 * SLABQ];  // fragment-packed fp16 hi/lo weights
__device__ float g_eout[2 * CB * 256];

// ---------------------------------------------------------------------------
__device__ __forceinline__ unsigned packh(__half a, __half b) {
    return (unsigned)__half_as_ushort(a) | ((unsigned)__half_as_ushort(b) << 16);
}

__device__ __forceinline__ void mma_f16(float (&c)[4], const uint32_t (&a)[4],
                                        uint32_t b0, uint32_t b1) {
    asm volatile(
        "mma.sync.aligned.m16n8k16.row.col.f32.f16.f16.f32 "
        "{%0,%1,%2,%3}, {%4,%5,%6,%7}, {%8,%9}, {%0,%1,%2,%3};"
        : "+f"(c[0]), "+f"(c[1]), "+f"(c[2]), "+f"(c[3])
        : "r"(a[0]), "r"(a[1]), "r"(a[2]), "r"(a[3]), "r"(b0), "r"(b1));
}

// Stage one K=32 chunk (2048 uint4 = 32KB) into Bs.
__device__ __forceinline__ void prefetch_chunk(const uint4* __restrict__ Wp, int cc,
                                               uint4* bs, int tid) {
    unsigned dst = (unsigned)__cvta_generic_to_shared(bs);
    const uint4* src = Wp + cc * CHQ;
#pragma unroll
    for (int i = 0; i < 8; i++) {
        int idx = i * NT + tid;
        asm volatile("cp.async.cg.shared.global [%0], [%1], 16;"
                     :: "r"(dst + idx * 16), "l"(src + idx));
    }
    asm volatile("cp.async.commit_group;");
}

// ---------------------------------------------------------------------------
// 64x256x256 GEMM, fp16 3-term split (ah*bh + ah*bl + al*bh), m16n8k16.
// A: two fp16 smem planes [64][APH]. B: pre-packed fragments, per k16-step st,
// n-tile nt, lane: uint4 {bh0,bh1,bl0,bl1}; uint4 index = st*1024 + nt*32 + lane
//   with k0 = st*16 + (lane&3)*2 (+1, +8, +9), n = nt*8 + (lane>>2).
// C layout identical to m16n8k8: row = g + h*8 (+m*16+wm*32), col = tg*2+q.
// ---------------------------------------------------------------------------
__device__ __forceinline__ void gemm_core(const uint4* __restrict__ Wp,
                                          const __half* __restrict__ Ah,
                                          const __half* __restrict__ Al,
                                          uint4* Bs, float (&c)[2][8][4],
                                          int wm, int wn, int lane, int tid)
{
    int g  = lane >> 2;
    int tg = lane & 3;
#pragma unroll
    for (int m = 0; m < 2; m++)
#pragma unroll
        for (int t = 0; t < 8; t++)
#pragma unroll
            for (int k = 0; k < 4; k++) c[m][t][k] = 0.f;

    prefetch_chunk(Wp, 0, Bs, tid);

    for (int cc = 0; cc < 8; cc++) {
        if (cc < 7) {
            prefetch_chunk(Wp, cc + 1, Bs + ((cc + 1) % NBUF) * CHQ, tid);
            asm volatile("cp.async.wait_group 1;" ::: "memory");
        } else {
            asm volatile("cp.async.wait_group 0;" ::: "memory");
        }
        __syncthreads();

        const uint4* bb = Bs + (cc % NBUF) * CHQ;
#pragma unroll
        for (int s = 0; s < 2; s++) {
            int kb = cc * 32 + s * 16;
            uint32_t ah_[2][4], al_[2][4];
#pragma unroll
            for (int m = 0; m < 2; m++) {
                const __half* pa = Ah + (wm * 32 + m * 16 + g) * APH + kb + tg * 2;
                ah_[m][0] = *reinterpret_cast<const uint32_t*>(pa);
                ah_[m][1] = *reinterpret_cast<const uint32_t*>(pa + 8 * APH);
                ah_[m][2] = *reinterpret_cast<const uint32_t*>(pa + 8);
                ah_[m][3] = *reinterpret_cast<const uint32_t*>(pa + 8 * APH + 8);
                const __half* pl = Al + (wm * 32 + m * 16 + g) * APH + kb + tg * 2;
                al_[m][0] = *reinterpret_cast<const uint32_t*>(pl);
                al_[m][1] = *reinterpret_cast<const uint32_t*>(pl + 8 * APH);
                al_[m][2] = *reinterpret_cast<const uint32_t*>(pl + 8);
                al_[m][3] = *reinterpret_cast<const uint32_t*>(pl + 8 * APH + 8);
            }
            const uint4* bp = bb + s * 1024 + wn * 256 + lane;
#pragma unroll
            for (int t = 0; t < 8; t++) {
                uint4 bv = bp[t * 32];
#pragma unroll
                for (int m = 0; m < 2; m++) {
                    mma_f16(c[m][t], ah_[m], bv.x, bv.y);   // ah*bh
                    mma_f16(c[m][t], ah_[m], bv.z, bv.w);   // ah*bl
                    mma_f16(c[m][t], al_[m], bv.x, bv.y);   // al*bh
                }
            }
        }
    }
}

// ---------------------------------------------------------------------------
// prep: zero counters; pack 25 slabs into fp16 hi/lo fragment uint4s.
// grid (64, 25) x 256; one uint4 per thread.
// ---------------------------------------------------------------------------
__global__ void prep_kernel(const float* __restrict__ gw1,
                            const float* __restrict__ w1,
                            const float* __restrict__ w2,
                            const float* __restrict__ w3)
{
    int tid = threadIdx.x;
    if (blockIdx.x == 0 && blockIdx.y == 0) {
        if (tid < CE) g_counts[tid] = 0;
        if (tid == CE) g_nfix = 0;
    }
    int slab = blockIdx.y;
    const float* src;
    if (slab == 0) src = gw1;
    else {
        int e = (slab - 1) / 3, l = (slab - 1) % 3;
        src = (l == 0 ? w1 : (l == 1 ? w2 : w3)) + (size_t)e * 65536;
    }
    int idx  = blockIdx.x * NT + tid;      // 0..16383
    int lane = idx & 31;
    int nt   = (idx >> 5) & 31;
    int st   = idx >> 10;                  // 0..15
    int k0 = st * 16 + (lane & 3) * 2;
    int n  = nt * 8 + (lane >> 2);

    float v00 = src[(size_t)k0 * 256 + n];
    float v01 = src[(size_t)(k0 + 1) * 256 + n];
    float v10 = src[(size_t)(k0 + 8) * 256 + n];
    float v11 = src[(size_t)(k0 + 9) * 256 + n];
    __half h00 = __float2half_rn(v00), h01 = __float2half_rn(v01);
    __half h10 = __float2half_rn(v10), h11 = __float2half_rn(v11);
    __half l00 = __float2half_rn(v00 - __half2float(h00));
    __half l01 = __float2half_rn(v01 - __half2float(h01));
    __half l10 = __float2half_rn(v10 - __half2float(h10));
    __half l11 = __float2half_rn(v11 - __half2float(h11));
    uint4 o;
    o.x = packh(h00, h01); o.y = packh(h10, h11);
    o.z = packh(l00, l01); o.w = packh(l10, l11);
    g_wpack[(size_t)slab * SLABQ + idx] = o;
}

// ---------------------------------------------------------------------------
// Gating: fp16-split GEMM1 -> relu(+gb1) -> fp32 logits vs gw2 -> top-2;
// near-tie tokens flagged for exact fp32 fixup.
// ---------------------------------------------------------------------------
__global__ void __launch_bounds__(NT, 1)
gating_kernel(const float* __restrict__ x,
              const float* __restrict__ gb1,
              const float* __restrict__ gw2,
              const float* __restrict__ gb2)
{
    extern __shared__ char smraw[];
    __half* Ah = (__half*)smraw;
    __half* Al = Ah + BM * APH;
    uint4*  Bs = (uint4*)(smraw + 2 * BM * APH * 2);

    __shared__ float gw2s[256 * 8];
    __shared__ float gb1s[256];
    __shared__ float lgS[4][BM][8];

    int tid  = threadIdx.x;
    int wid  = tid >> 5;
    int lane = tid & 31;
    int wm = wid >> 2, wn = wid & 3;
    int g = lane >> 2, tg = lane & 3;
    int t0 = blockIdx.x * BM;

    for (int i = tid; i < 2048; i += NT) gw2s[i] = gw2[i];
    if (tid < 256) gb1s[tid] = gb1[tid];

    // A = x rows, fp16 hi/lo split
    const float4* x4 = reinterpret_cast<const float4*>(x);
    for (int i = tid; i < BM * 64; i += NT) {
        int rr = i >> 6, c4 = i & 63;
        float4 v = __ldg(&x4[(size_t)(t0 + rr) * 64 + c4]);
        __half hx = __float2half_rn(v.x), hy = __float2half_rn(v.y);
        __half hz = __float2half_rn(v.z), hw = __float2half_rn(v.w);
        uint2 hh, ll;
        hh.x = packh(hx, hy); hh.y = packh(hz, hw);
        ll.x = packh(__float2half_rn(v.x - __half2float(hx)),
                     __float2half_rn(v.y - __half2float(hy)));
        ll.y = packh(__float2half_rn(v.z - __half2float(hz)),
                     __float2half_rn(v.w - __half2float(hw)));
        *reinterpret_cast<uint2*>(Ah + rr * APH + c4 * 4) = hh;
        *reinterpret_cast<uint2*>(Al + rr * APH + c4 * 4) = ll;
    }
    __syncthreads();

    float c[2][8][4];
    gemm_core(g_wpack, Ah, Al, Bs, c, wm, wn, lane, tid);

    // logits partials (fp32)
    float lg[2][2][8];
#pragma unroll
    for (int m = 0; m < 2; m++)
#pragma unroll
        for (int h = 0; h < 2; h++)
#pragma unroll
            for (int e = 0; e < 8; e++) lg[m][h][e] = 0.f;

#pragma unroll
    for (int m = 0; m < 2; m++)
#pragma unroll
        for (int t = 0; t < 8; t++) {
            int colb = wn * 64 + t * 8 + tg * 2;
#pragma unroll
            for (int h = 0; h < 2; h++)
#pragma unroll
                for (int q = 0; q < 2; q++) {
                    int col = colb + q;
                    float hv = fmaxf(c[m][t][h * 2 + q] + gb1s[col], 0.f);
                    const float4* gp = reinterpret_cast<const float4*>(gw2s + col * 8);
                    float4 p0 = gp[0], p1 = gp[1];
                    lg[m][h][0] += hv * p0.x; lg[m][h][1] += hv * p0.y;
                    lg[m][h][2] += hv * p0.z; lg[m][h][3] += hv * p0.w;
                    lg[m][h][4] += hv * p1.x; lg[m][h][5] += hv * p1.y;
                    lg[m][h][6] += hv * p1.z; lg[m][h][7] += hv * p1.w;
                }
        }
#pragma unroll
    for (int off = 1; off <= 2; off <<= 1)
#pragma unroll
        for (int m = 0; m < 2; m++)
#pragma unroll
            for (int h = 0; h < 2; h++)
#pragma unroll
                for (int e = 0; e < 8; e++)
                    lg[m][h][e] += __shfl_xor_sync(0xffffffffu, lg[m][h][e], off);
    if (tg == 0) {
#pragma unroll
        for (int m = 0; m < 2; m++)
#pragma unroll
            for (int h = 0; h < 2; h++) {
                int row = wm * 32 + m * 16 + g + h * 8;
#pragma unroll
                for (int e = 0; e < 8; e++) lgS[wn][row][e] = lg[m][h][e];
            }
    }
    __syncthreads();

    if (tid < BM) {
        float l[CE];
#pragma unroll
        for (int e = 0; e < CE; e++)
            l[e] = lgS[0][tid][e] + lgS[1][tid][e] + lgS[2][tid][e] + lgS[3][tid][e]
                 + __ldg(&gb2[e]);
        int i0 = 0;
#pragma unroll
        for (int e = 1; e < CE; e++) if (l[e] > l[i0]) i0 = e;
        int i1 = (i0 == 0) ? 1 : 0;
#pragma unroll
        for (int e = 0; e < CE; e++) if (e != i0 && l[e] > l[i1]) i1 = e;
        float l2v = -1e30f;
#pragma unroll
        for (int e = 0; e < CE; e++)
            if (e != i0 && e != i1 && l[e] > l2v) l2v = l[e];
        float w0 = 1.f / (1.f + expf(l[i1] - l[i0]));
        int tok = t0 + tid;
        g_sel[tok] = i0 | (i1 << 8);
        g_w0[tok]  = w0;
        if (l[i1] - l2v < 1e-4f) {
            int p = atomicAdd(&g_nfix, 1);
            g_fixlist[p] = tok;
        }
    }
}

// ---------------------------------------------------------------------------
// Exact-fp32 gating recompute for flagged near-tie tokens.
// ---------------------------------------------------------------------------
__global__ void fixup_kernel(const float* __restrict__ x,
                             const float* __restrict__ gw1,
                             const float* __restrict__ gb1,
                             const float* __restrict__ gw2,
                             const float* __restrict__ gb2)
{
    __shared__ float hS[256];
    __shared__ float lg8[CE];
    int nf = g_nfix;
    int tid = threadIdx.x;
    for (int i = blockIdx.x; i < nf; i += gridDim.x) {
        int t = g_fixlist[i];
        const float* xr = x + (size_t)t * 256;
        float acc = 0.f;
        for (int k = 0; k < 256; k++)
            acc = fmaf(__ldg(&xr[k]), __ldg(&gw1[(size_t)k * 256 + tid]), acc);
        hS[tid] = fmaxf(acc + __ldg(&gb1[tid]), 0.f);
        __syncthreads();
        int wid = tid >> 5, lane = tid & 31;
        float s = 0.f;
        for (int j = lane; j < 256; j += 32) s += hS[j] * __ldg(&gw2[j * 8 + wid]);
#pragma unroll
        for (int o = 16; o > 0; o >>= 1) s += __shfl_xor_sync(0xffffffffu, s, o);
        if (lane == 0) lg8[wid] = s + __ldg(&gb2[wid]);
        __syncthreads();
        if (tid == 0) {
            float l[CE];
#pragma unroll
            for (int e = 0; e < CE; e++) l[e] = lg8[e];
            int i0 = 0;
#pragma unroll
            for (int e = 1; e < CE; e++) if (l[e] > l[i0]) i0 = e;
            int i1 = (i0 == 0) ? 1 : 0;
#pragma unroll
            for (int e = 0; e < CE; e++) if (e != i0 && l[e] > l[i1]) i1 = e;
            g_sel[t] = i0 | (i1 << 8);
            g_w0[t]  = 1.f / (1.f + expf(l[i1] - l[i0]));
        }
        __syncthreads();
    }
}

// ---------------------------------------------------------------------------
__global__ void route_kernel()
{
    __shared__ int cnt[CE], baseI[CE];
    int tid = threadIdx.x;
    int t = blockIdx.x * NT + tid;
    if (tid < CE) cnt[tid] = 0;
    __syncthreads();
    int sel = g_sel[t];
    int e0 = sel & 255, e1 = sel >> 8;
    float w0 = g_w0[t];
    int p0 = atomicAdd(&cnt[e0], 1);
    int p1 = atomicAdd(&cnt[e1], 1);
    __syncthreads();
    if (tid < CE) baseI[tid] = atomicAdd(&g_counts[tid], cnt[tid]);
    __syncthreads();
    int q0 = e0 * CB + baseI[e0] + p0;
    g_rtok[q0] = t; g_rw[q0] = w0;        g_rdst[q0] = 2 * t;
    int q1 = e1 * CB + baseI[e1] + p1;
    g_rtok[q1] = t; g_rw[q1] = 1.f - w0;  g_rdst[q1] = 2 * t + 1;
}

// ---------------------------------------------------------------------------
// Expert kernel: fused 3-layer MLP on routed 64-token tiles (fp16-split GEMMs);
// LN in registers; weighted rows to g_eout (no atomics).
// ---------------------------------------------------------------------------
__global__ void __launch_bounds__(NT, 1)
expert_kernel(const float* __restrict__ x,
              const float* __restrict__ b1, const float* __restrict__ g1,
              const float* __restrict__ be1,
              const float* __restrict__ b2, const float* __restrict__ g2,
              const float* __restrict__ be2,
              const float* __restrict__ b3)
{
    int e = blockIdx.y;
    int count = g_counts[e];
    int t0 = blockIdx.x * BM;
    if (t0 >= count) return;
    int mrows = min(BM, count - t0);

    extern __shared__ char smraw[];
    __half* Ah = (__half*)smraw;
    __half* Al = Ah + BM * APH;
    uint4*  Bs = (uint4*)(smraw + 2 * BM * APH * 2);

    __shared__ int   tokS[BM];
    __shared__ float wS[BM];
    __shared__ int   dstS[BM];
    __shared__ float biasS[256], gamS[256], betS[256];
    __shared__ float redS[4][BM][2];
    __shared__ float mrS[BM][2];

    int tid  = threadIdx.x;
    int wid  = tid >> 5;
    int lane = tid & 31;
    int wm = wid >> 2, wn = wid & 3;
    int g = lane >> 2, tg = lane & 3;

    if (tid < BM) {
        bool v = tid < mrows;
        int q = e * CB + t0 + tid;
        tokS[tid] = v ? g_rtok[q] : 0;
        wS[tid]   = v ? g_rw[q]   : 0.f;
        dstS[tid] = v ? g_rdst[q] : 0;
    }
    __syncthreads();

    // A = gathered x rows, fp16 hi/lo split
    const float4* x4 = reinterpret_cast<const float4*>(x);
    for (int i = tid; i < BM * 64; i += NT) {
        int rr = i >> 6, c4 = i & 63;
        float4 v = __ldg(&x4[(size_t)tokS[rr] * 64 + c4]);
        __half hx = __float2half_rn(v.x), hy = __float2half_rn(v.y);
        __half hz = __float2half_rn(v.z), hw = __float2half_rn(v.w);
        uint2 hh, ll;
        hh.x = packh(hx, hy); hh.y = packh(hz, hw);
        ll.x = packh(__float2half_rn(v.x - __half2float(hx)),
                     __float2half_rn(v.y - __half2float(hy)));
        ll.y = packh(__float2half_rn(v.z - __half2float(hz)),
                     __float2half_rn(v.w - __half2float(hw)));
        *reinterpret_cast<uint2*>(Ah + rr * APH + c4 * 4) = hh;
        *reinterpret_cast<uint2*>(Al + rr * APH + c4 * 4) = ll;
    }

    float c[2][8][4];

    for (int l = 0; l < 3; l++) {
        if (tid < 256) {
            biasS[tid] = (l == 0 ? b1 : (l == 1 ? b2 : b3))[e * 256 + tid];
            if (l < 2) {
                gamS[tid] = (l == 0 ? g1 : g2)[e * 256 + tid];
                betS[tid] = (l == 0 ? be1 : be2)[e * 256 + tid];
            }
        }
        __syncthreads();

        gemm_core(g_wpack + (size_t)(1 + e * 3 + l) * SLABQ, Ah, Al, Bs,
                  c, wm, wn, lane, tid);

        if (l < 2) {
            float s1[2][2] = {{0.f, 0.f}, {0.f, 0.f}};
            float s2[2][2] = {{0.f, 0.f}, {0.f, 0.f}};
#pragma unroll
            for (int m = 0; m < 2; m++)
#pragma unroll
                for (int t = 0; t < 8; t++) {
                    int colb = wn * 64 + t * 8 + tg * 2;
#pragma unroll
                    for (int h = 0; h < 2; h++)
#pragma unroll
                        for (int q = 0; q < 2; q++) {
                            float v = c[m][t][h * 2 + q] + biasS[colb + q];
                            c[m][t][h * 2 + q] = v;
                            s1[m][h] += v; s2[m][h] += v * v;
                        }
                }
#pragma unroll
            for (int off = 1; off <= 2; off <<= 1)
#pragma unroll
                for (int m = 0; m < 2; m++)
#pragma unroll
                    for (int h = 0; h < 2; h++) {
                        s1[m][h] += __shfl_xor_sync(0xffffffffu, s1[m][h], off);
                        s2[m][h] += __shfl_xor_sync(0xffffffffu, s2[m][h], off);
                    }
            if (tg == 0) {
#pragma unroll
                for (int m = 0; m < 2; m++)
#pragma unroll
                    for (int h = 0; h < 2; h++) {
                        int row = wm * 32 + m * 16 + g + h * 8;
                        redS[wn][row][0] = s1[m][h];
                        redS[wn][row][1] = s2[m][h];
                    }
            }
            __syncthreads();
            if (tid < BM) {
                float a = redS[0][tid][0] + redS[1][tid][0] + redS[2][tid][0] + redS[3][tid][0];
                float b = redS[0][tid][1] + redS[1][tid][1] + redS[2][tid][1] + redS[3][tid][1];
                float mean = a * (1.f / 256.f);
                float var  = b * (1.f / 256.f) - mean * mean;
                mrS[tid][0] = mean;
                mrS[tid][1] = rsqrtf(var + 1e-5f);
            }
            __syncthreads();
            // normalize + relu + fp16 split -> Ah/Al (next layer A)
#pragma unroll
            for (int m = 0; m < 2; m++)
#pragma unroll
                for (int h = 0; h < 2; h++) {
                    int row = wm * 32 + m * 16 + g + h * 8;
                    float mean = mrS[row][0], rs = mrS[row][1];
#pragma unroll
                    for (int t = 0; t < 8; t++) {
                        int colb = wn * 64 + t * 8 + tg * 2;
                        float h0 = fmaxf((c[m][t][h * 2 + 0] - mean) * rs * gamS[colb]
                                         + betS[colb], 0.f);
                        float h1 = fmaxf((c[m][t][h * 2 + 1] - mean) * rs * gamS[colb + 1]
                                         + betS[colb + 1], 0.f);
                        __half hi0 = __float2half_rn(h0);
                        __half hi1 = __float2half_rn(h1);
                        __half lo0 = __float2half_rn(h0 - __half2float(hi0));
                        __half lo1 = __float2half_rn(h1 - __half2float(hi1));
                        *reinterpret_cast<uint32_t*>(Ah + row * APH + colb) = packh(hi0, hi1);
                        *reinterpret_cast<uint32_t*>(Al + row * APH + colb) = packh(lo0, lo1);
                    }
                }
            __syncthreads();
        }
    }

    // final: +b3, gate weight, store rows to g_eout[dst]
#pragma unroll
    for (int m = 0; m < 2; m++)
#pragma unroll
        for (int h = 0; h < 2; h++) {
            int row = wm * 32 + m * 16 + g + h * 8;
            if (row < mrows) {
                float wgt = wS[row];
                float* orow = g_eout + (size_t)dstS[row] * 256;
#pragma unroll
                for (int t = 0; t < 8; t++) {
                    int colb = wn * 64 + t * 8 + tg * 2;
                    float2 v = make_float2(
                        wgt * (c[m][t][h * 2 + 0] + biasS[colb]),
                        wgt * (c[m][t][h * 2 + 1] + biasS[colb + 1]));
                    *reinterpret_cast<float2*>(orow + colb) = v;
                }
            }
        }
}

// ---------------------------------------------------------------------------
__global__ void combine_kernel(float* __restrict__ out)
{
    int i = blockIdx.x * blockDim.x + threadIdx.x;   // CB*64 float4s
    if (i >= CB * 64) return;
    int t = i >> 6, c4 = i & 63;
    const float4* e4 = reinterpret_cast<const float4*>(g_eout);
    float4 a = e4[(size_t)(2 * t) * 64 + c4];
    float4 b = e4[(size_t)(2 * t + 1) * 64 + c4];
    reinterpret_cast<float4*>(out)[i] =
        make_float4(a.x + b.x, a.y + b.y, a.z + b.z, a.w + b.w);
}

// ---------------------------------------------------------------------------
extern "C" void kernel_launch(void* const* d_in, const int* in_sizes, int n_in,
                              void* d_out, int out_size)
{
    const float* x   = (const float*)d_in[0];
    const float* gw1 = (const float*)d_in[1];
    const float* gb1 = (const float*)d_in[2];
    const float* gw2 = (const float*)d_in[3];
    const float* gb2 = (const float*)d_in[4];
    const float* w1  = (const float*)d_in[5];
    const float* b1  = (const float*)d_in[6];
    const float* g1  = (const float*)d_in[7];
    const float* be1 = (const float*)d_in[8];
    const float* w2  = (const float*)d_in[9];
    const float* b2  = (const float*)d_in[10];
    const float* g2  = (const float*)d_in[11];
    const float* be2 = (const float*)d_in[12];
    const float* w3  = (const float*)d_in[13];
    const float* b3  = (const float*)d_in[14];
    float* out = (float*)d_out;

    // dynamic smem: 2 A planes (fp16) + 3 B buffers
    const int smem_bytes = 2 * BM * APH * 2 + NBUF * CHQ * 16;   // 67584 + 98304

    cudaFuncSetAttribute(gating_kernel,
                         cudaFuncAttributeMaxDynamicSharedMemorySize, smem_bytes);
    cudaFuncSetAttribute(expert_kernel,
                         cudaFuncAttributeMaxDynamicSharedMemorySize, smem_bytes);

    prep_kernel<<<dim3(64, 25), NT>>>(gw1, w1, w2, w3);

    gating_kernel<<<CB / BM, NT, smem_bytes>>>(x, gb1, gw2, gb2);

    fixup_kernel<<<64, NT>>>(x, gw1, gb1, gw2, gb2);

    route_kernel<<<CB / NT, NT>>>();

    dim3 egrid(CB / BM, CE);
    expert_kernel<<<egrid, NT, smem_bytes>>>(x, b1, g1, be1, b2, g2, be2, b3);

    combine_kernel<<<(CB * 64 + NT - 1) / NT, NT>>>(out);
}

// round 7
// speedup vs baseline: 2.1006x; 1.0727x over previous
#include <cuda_runtime.h>
#include <cuda_fp16.h>
#include <cstdint>
#include <math.h>

#define CB 32768
#define CE 8
constexpr int NT   = 512;     // threads per block (16 warps)
constexpr int BM   = 128;     // token rows per tile
constexpr int APH  = 264;     // A row stride in fp16 units (conflict-free pad)
constexpr int SLABQ = 16384;  // uint4 per packed 256x256 slab
constexpr int CHQ   = 2048;   // uint4 per K=32 chunk
constexpr int NBUF  = 2;      // B buffers (safe: prefetch issued after barrier)

// dynamic smem layout (bytes)
constexpr int A_BYTES  = 2 * BM * APH * 2;       // 135168 (Ah+Al)
constexpr int B_BYTES  = NBUF * CHQ * 16;        // 65536
constexpr int SMEM_EXP = A_BYTES + B_BYTES;      // 200704
constexpr int SMEM_GAT = SMEM_EXP + 2048 * 4 + 256 * 4 + 4 * BM * 8 * 4; // +gw2s+gb1s+lgS = 226304

// ---------------------------------------------------------------------------
// Device scratch (static, graph-capturable)
// ---------------------------------------------------------------------------
__device__ int   g_counts[CE];
__device__ int   g_nfix;
__device__ int   g_fixlist[CB];
__device__ int   g_sel[CB];            // i0 | (i1<<8)
__device__ float g_w0[CB];
__device__ int   g_rtok[CE * CB];
__device__ float g_rw[CE * CB];
__device__ int   g_rdst[CE * CB];
__device__ uint4 g_wpack[25 * SLABQ];  // fragment-packed fp16 hi/lo weights
__device__ float g_eout[2 * CB * 256];

// ---------------------------------------------------------------------------
__device__ __forceinline__ unsigned packh(__half a, __half b) {
    return (unsigned)__half_as_ushort(a) | ((unsigned)__half_as_ushort(b) << 16);
}

__device__ __forceinline__ void mma_f16(float (&c)[4], const uint32_t (&a)[4],
                                        uint32_t b0, uint32_t b1) {
    asm volatile(
        "mma.sync.aligned.m16n8k16.row.col.f32.f16.f16.f32 "
        "{%0,%1,%2,%3}, {%4,%5,%6,%7}, {%8,%9}, {%0,%1,%2,%3};"
        : "+f"(c[0]), "+f"(c[1]), "+f"(c[2]), "+f"(c[3])
        : "r"(a[0]), "r"(a[1]), "r"(a[2]), "r"(a[3]), "r"(b0), "r"(b1));
}

// Stage one K=32 chunk (2048 uint4 = 32KB) into bs.
__device__ __forceinline__ void prefetch_chunk(const uint4* __restrict__ Wp, int cc,
                                               uint4* bs, int tid) {
    unsigned dst = (unsigned)__cvta_generic_to_shared(bs);
    const uint4* src = Wp + cc * CHQ;
#pragma unroll
    for (int i = 0; i < 4; i++) {
        int idx = i * NT + tid;
        asm volatile("cp.async.cg.shared.global [%0], [%1], 16;"
                     :: "r"(dst + idx * 16), "l"(src + idx));
    }
    asm volatile("cp.async.commit_group;");
}

// ---------------------------------------------------------------------------
// 128x256x256 GEMM, fp16 3-term split (ah*bh + ah*bl + al*bh), m16n8k16.
// 16 warps: wm = wid>>2 (rows wm*32..+31), wn = wid&3 (cols wn*64..+63).
// B fragments pre-packed: uint4 {bh0,bh1,bl0,bl1} at index st*1024 + nt*32 + lane,
//   k0 = st*16 + (lane&3)*2 (+1,+8,+9), n = nt*8 + (lane>>2).
// Buffer protocol per chunk cc: wait_group 0 (chunk cc arrived) -> barrier ->
// prefetch cc+1 (into the buffer everyone finished with before this barrier)
// -> consume cc. Safe with NBUF=2, fully overlapped.
// ---------------------------------------------------------------------------
__device__ __forceinline__ void gemm_core(const uint4* __restrict__ Wp,
                                          const __half* __restrict__ Ah,
                                          const __half* __restrict__ Al,
                                          uint4* Bs, float (&c)[2][8][4],
                                          int wm, int wn, int lane, int tid)
{
    int g  = lane >> 2;
    int tg = lane & 3;
#pragma unroll
    for (int m = 0; m < 2; m++)
#pragma unroll
        for (int t = 0; t < 8; t++)
#pragma unroll
            for (int k = 0; k < 4; k++) c[m][t][k] = 0.f;

    prefetch_chunk(Wp, 0, Bs, tid);

    for (int cc = 0; cc < 8; cc++) {
        asm volatile("cp.async.wait_group 0;" ::: "memory");
        __syncthreads();
        if (cc < 7)
            prefetch_chunk(Wp, cc + 1, Bs + ((cc + 1) & 1) * CHQ, tid);

        const uint4* bb = Bs + (cc & 1) * CHQ;
#pragma unroll
        for (int s = 0; s < 2; s++) {
            int kb = cc * 32 + s * 16;
            uint32_t ah_[2][4], al_[2][4];
#pragma unroll
            for (int m = 0; m < 2; m++) {
                const __half* pa = Ah + (wm * 32 + m * 16 + g) * APH + kb + tg * 2;
                ah_[m][0] = *reinterpret_cast<const uint32_t*>(pa);
                ah_[m][1] = *reinterpret_cast<const uint32_t*>(pa + 8 * APH);
                ah_[m][2] = *reinterpret_cast<const uint32_t*>(pa + 8);
                ah_[m][3] = *reinterpret_cast<const uint32_t*>(pa + 8 * APH + 8);
                const __half* pl = Al + (wm * 32 + m * 16 + g) * APH + kb + tg * 2;
                al_[m][0] = *reinterpret_cast<const uint32_t*>(pl);
                al_[m][1] = *reinterpret_cast<const uint32_t*>(pl + 8 * APH);
                al_[m][2] = *reinterpret_cast<const uint32_t*>(pl + 8);
                al_[m][3] = *reinterpret_cast<const uint32_t*>(pl + 8 * APH + 8);
            }
            const uint4* bp = bb + s * 1024 + wn * 256 + lane;
#pragma unroll
            for (int t = 0; t < 8; t++) {
                uint4 bv = bp[t * 32];
#pragma unroll
                for (int m = 0; m < 2; m++) {
                    mma_f16(c[m][t], ah_[m], bv.x, bv.y);   // ah*bh
                    mma_f16(c[m][t], ah_[m], bv.z, bv.w);   // ah*bl
                    mma_f16(c[m][t], al_[m], bv.x, bv.y);   // al*bh
                }
            }
        }
        __syncthreads();   // all reads of buf cc done before it is refilled
    }
}

// ---------------------------------------------------------------------------
// prep: zero counters; pack 25 slabs into fp16 hi/lo fragment uint4s.
// grid (64, 25) x 256; one uint4 per thread.
// ---------------------------------------------------------------------------
__global__ void prep_kernel(const float* __restrict__ gw1,
                            const float* __restrict__ w1,
                            const float* __restrict__ w2,
                            const float* __restrict__ w3)
{
    int tid = threadIdx.x;
    if (blockIdx.x == 0 && blockIdx.y == 0) {
        if (tid < CE) g_counts[tid] = 0;
        if (tid == CE) g_nfix = 0;
    }
    int slab = blockIdx.y;
    const float* src;
    if (slab == 0) src = gw1;
    else {
        int e = (slab - 1) / 3, l = (slab - 1) % 3;
        src = (l == 0 ? w1 : (l == 1 ? w2 : w3)) + (size_t)e * 65536;
    }
    int idx  = blockIdx.x * 256 + tid;     // 0..16383
    int lane = idx & 31;
    int nt   = (idx >> 5) & 31;
    int st   = idx >> 10;                  // 0..15
    int k0 = st * 16 + (lane & 3) * 2;
    int n  = nt * 8 + (lane >> 2);

    float v00 = src[(size_t)k0 * 256 + n];
    float v01 = src[(size_t)(k0 + 1) * 256 + n];
    float v10 = src[(size_t)(k0 + 8) * 256 + n];
    float v11 = src[(size_t)(k0 + 9) * 256 + n];
    __half h00 = __float2half_rn(v00), h01 = __float2half_rn(v01);
    __half h10 = __float2half_rn(v10), h11 = __float2half_rn(v11);
    __half l00 = __float2half_rn(v00 - __half2float(h00));
    __half l01 = __float2half_rn(v01 - __half2float(h01));
    __half l10 = __float2half_rn(v10 - __half2float(h10));
    __half l11 = __float2half_rn(v11 - __half2float(h11));
    uint4 o;
    o.x = packh(h00, h01); o.y = packh(h10, h11);
    o.z = packh(l00, l01); o.w = packh(l10, l11);
    g_wpack[(size_t)slab * SLABQ + idx] = o;
}

// ---------------------------------------------------------------------------
// Gating: fp16-split GEMM1 -> relu(+gb1) -> fp32 logits vs gw2 -> top-2;
// near-tie tokens flagged for exact fp32 fixup.
// ---------------------------------------------------------------------------
__global__ void __launch_bounds__(NT, 1)
gating_kernel(const float* __restrict__ x,
              const float* __restrict__ gb1,
              const float* __restrict__ gw2,
              const float* __restrict__ gb2)
{
    extern __shared__ char smraw[];
    __half* Ah   = (__half*)smraw;
    __half* Al   = Ah + BM * APH;
    uint4*  Bs   = (uint4*)(smraw + A_BYTES);
    float*  gw2s = (float*)(smraw + SMEM_EXP);            // 2048
    float*  gb1s = gw2s + 2048;                           // 256
    float (*lgS)[BM][8] = (float (*)[BM][8])(gb1s + 256); // [4][BM][8]

    int tid  = threadIdx.x;
    int wid  = tid >> 5;
    int lane = tid & 31;
    int wm = wid >> 2, wn = wid & 3;
    int g = lane >> 2, tg = lane & 3;
    int t0 = blockIdx.x * BM;

    for (int i = tid; i < 2048; i += NT) gw2s[i] = gw2[i];
    if (tid < 256) gb1s[tid] = gb1[tid];

    // A = x rows, fp16 hi/lo split
    const float4* x4 = reinterpret_cast<const float4*>(x);
    for (int i = tid; i < BM * 64; i += NT) {
        int rr = i >> 6, c4 = i & 63;
        float4 v = __ldg(&x4[(size_t)(t0 + rr) * 64 + c4]);
        __half hx = __float2half_rn(v.x), hy = __float2half_rn(v.y);
        __half hz = __float2half_rn(v.z), hw = __float2half_rn(v.w);
        uint2 hh, ll;
        hh.x = packh(hx, hy); hh.y = packh(hz, hw);
        ll.x = packh(__float2half_rn(v.x - __half2float(hx)),
                     __float2half_rn(v.y - __half2float(hy)));
        ll.y = packh(__float2half_rn(v.z - __half2float(hz)),
                     __float2half_rn(v.w - __half2float(hw)));
        *reinterpret_cast<uint2*>(Ah + rr * APH + c4 * 4) = hh;
        *reinterpret_cast<uint2*>(Al + rr * APH + c4 * 4) = ll;
    }
    __syncthreads();

    float c[2][8][4];
    gemm_core(g_wpack, Ah, Al, Bs, c, wm, wn, lane, tid);

    // logits partials (fp32)
    float lg[2][2][8];
#pragma unroll
    for (int m = 0; m < 2; m++)
#pragma unroll
        for (int h = 0; h < 2; h++)
#pragma unroll
            for (int e = 0; e < 8; e++) lg[m][h][e] = 0.f;

#pragma unroll
    for (int m = 0; m < 2; m++)
#pragma unroll
        for (int t = 0; t < 8; t++) {
            int colb = wn * 64 + t * 8 + tg * 2;
#pragma unroll
            for (int h = 0; h < 2; h++)
#pragma unroll
                for (int q = 0; q < 2; q++) {
                    int col = colb + q;
                    float hv = fmaxf(c[m][t][h * 2 + q] + gb1s[col], 0.f);
                    const float4* gp = reinterpret_cast<const float4*>(gw2s + col * 8);
                    float4 p0 = gp[0], p1 = gp[1];
                    lg[m][h][0] += hv * p0.x; lg[m][h][1] += hv * p0.y;
                    lg[m][h][2] += hv * p0.z; lg[m][h][3] += hv * p0.w;
                    lg[m][h][4] += hv * p1.x; lg[m][h][5] += hv * p1.y;
                    lg[m][h][6] += hv * p1.z; lg[m][h][7] += hv * p1.w;
                }
        }
#pragma unroll
    for (int off = 1; off <= 2; off <<= 1)
#pragma unroll
        for (int m = 0; m < 2; m++)
#pragma unroll
            for (int h = 0; h < 2; h++)
#pragma unroll
                for (int e = 0; e < 8; e++)
                    lg[m][h][e] += __shfl_xor_sync(0xffffffffu, lg[m][h][e], off);
    if (tg == 0) {
#pragma unroll
        for (int m = 0; m < 2; m++)
#pragma unroll
            for (int h = 0; h < 2; h++) {
                int row = wm * 32 + m * 16 + g + h * 8;
#pragma unroll
                for (int e = 0; e < 8; e++) lgS[wn][row][e] = lg[m][h][e];
            }
    }
    __syncthreads();

    if (tid < BM) {
        float l[CE];
#pragma unroll
        for (int e = 0; e < CE; e++)
            l[e] = lgS[0][tid][e] + lgS[1][tid][e] + lgS[2][tid][e] + lgS[3][tid][e]
                 + __ldg(&gb2[e]);
        int i0 = 0;
#pragma unroll
        for (int e = 1; e < CE; e++) if (l[e] > l[i0]) i0 = e;
        int i1 = (i0 == 0) ? 1 : 0;
#pragma unroll
        for (int e = 0; e < CE; e++) if (e != i0 && l[e] > l[i1]) i1 = e;
        float l2v = -1e30f;
#pragma unroll
        for (int e = 0; e < CE; e++)
            if (e != i0 && e != i1 && l[e] > l2v) l2v = l[e];
        float w0 = 1.f / (1.f + expf(l[i1] - l[i0]));
        int tok = t0 + tid;
        g_sel[tok] = i0 | (i1 << 8);
        g_w0[tok]  = w0;
        if (l[i1] - l2v < 1e-4f) {
            int p = atomicAdd(&g_nfix, 1);
            g_fixlist[p] = tok;
        }
    }
}

// ---------------------------------------------------------------------------
// Exact-fp32 gating recompute for flagged near-tie tokens.
// ---------------------------------------------------------------------------
__global__ void fixup_kernel(const float* __restrict__ x,
                             const float* __restrict__ gw1,
                             const float* __restrict__ gb1,
                             const float* __restrict__ gw2,
                             const float* __restrict__ gb2)
{
    __shared__ float hS[256];
    __shared__ float lg8[CE];
    int nf = g_nfix;
    int tid = threadIdx.x;
    for (int i = blockIdx.x; i < nf; i += gridDim.x) {
        int t = g_fixlist[i];
        const float* xr = x + (size_t)t * 256;
        float acc = 0.f;
        for (int k = 0; k < 256; k++)
            acc = fmaf(__ldg(&xr[k]), __ldg(&gw1[(size_t)k * 256 + tid]), acc);
        hS[tid] = fmaxf(acc + __ldg(&gb1[tid]), 0.f);
        __syncthreads();
        int wid = tid >> 5, lane = tid & 31;
        float s = 0.f;
        for (int j = lane; j < 256; j += 32) s += hS[j] * __ldg(&gw2[j * 8 + wid]);
#pragma unroll
        for (int o = 16; o > 0; o >>= 1) s += __shfl_xor_sync(0xffffffffu, s, o);
        if (lane == 0) lg8[wid] = s + __ldg(&gb2[wid]);
        __syncthreads();
        if (tid == 0) {
            float l[CE];
#pragma unroll
            for (int e = 0; e < CE; e++) l[e] = lg8[e];
            int i0 = 0;
#pragma unroll
            for (int e = 1; e < CE; e++) if (l[e] > l[i0]) i0 = e;
            int i1 = (i0 == 0) ? 1 : 0;
#pragma unroll
            for (int e = 0; e < CE; e++) if (e != i0 && l[e] > l[i1]) i1 = e;
            g_sel[t] = i0 | (i1 << 8);
            g_w0[t]  = 1.f / (1.f + expf(l[i1] - l[i0]));
        }
        __syncthreads();
    }
}

// ---------------------------------------------------------------------------
__global__ void route_kernel()
{
    __shared__ int cnt[CE], baseI[CE];
    int tid = threadIdx.x;
    int t = blockIdx.x * 256 + tid;
    if (tid < CE) cnt[tid] = 0;
    __syncthreads();
    int sel = g_sel[t];
    int e0 = sel & 255, e1 = sel >> 8;
    float w0 = g_w0[t];
    int p0 = atomicAdd(&cnt[e0], 1);
    int p1 = atomicAdd(&cnt[e1], 1);
    __syncthreads();
    if (tid < CE) baseI[tid] = atomicAdd(&g_counts[tid], cnt[tid]);
    __syncthreads();
    int q0 = e0 * CB + baseI[e0] + p0;
    g_rtok[q0] = t; g_rw[q0] = w0;        g_rdst[q0] = 2 * t;
    int q1 = e1 * CB + baseI[e1] + p1;
    g_rtok[q1] = t; g_rw[q1] = 1.f - w0;  g_rdst[q1] = 2 * t + 1;
}

// ---------------------------------------------------------------------------
// Expert kernel: fused 3-layer MLP on routed 128-token tiles (fp16-split
// GEMMs); LN in registers; weighted rows to g_eout (no atomics).
// ---------------------------------------------------------------------------
__global__ void __launch_bounds__(NT, 1)
expert_kernel(const float* __restrict__ x,
              const float* __restrict__ b1, const float* __restrict__ g1,
              const float* __restrict__ be1,
              const float* __restrict__ b2, const float* __restrict__ g2,
              const float* __restrict__ be2,
              const float* __restrict__ b3)
{
    int e = blockIdx.y;
    int count = g_counts[e];
    int t0 = blockIdx.x * BM;
    if (t0 >= count) return;
    int mrows = min(BM, count - t0);

    extern __shared__ char smraw[];
    __half* Ah = (__half*)smraw;
    __half* Al = Ah + BM * APH;
    uint4*  Bs = (uint4*)(smraw + A_BYTES);

    __shared__ int   tokS[BM];
    __shared__ float wS[BM];
    __shared__ int   dstS[BM];
    __shared__ float biasS[256], gamS[256], betS[256];
    __shared__ float redS[4][BM][2];
    __shared__ float mrS[BM][2];

    int tid  = threadIdx.x;
    int wid  = tid >> 5;
    int lane = tid & 31;
    int wm = wid >> 2, wn = wid & 3;
    int g = lane >> 2, tg = lane & 3;

    if (tid < BM) {
        bool v = tid < mrows;
        int q = e * CB + t0 + tid;
        tokS[tid] = v ? g_rtok[q] : 0;
        wS[tid]   = v ? g_rw[q]   : 0.f;
        dstS[tid] = v ? g_rdst[q] : 0;
    }
    __syncthreads();

    // A = gathered x rows, fp16 hi/lo split
    const float4* x4 = reinterpret_cast<const float4*>(x);
    for (int i = tid; i < BM * 64; i += NT) {
        int rr = i >> 6, c4 = i & 63;
        float4 v = __ldg(&x4[(size_t)tokS[rr] * 64 + c4]);
        __half hx = __float2half_rn(v.x), hy = __float2half_rn(v.y);
        __half hz = __float2half_rn(v.z), hw = __float2half_rn(v.w);
        uint2 hh, ll;
        hh.x = packh(hx, hy); hh.y = packh(hz, hw);
        ll.x = packh(__float2half_rn(v.x - __half2float(hx)),
                     __float2half_rn(v.y - __half2float(hy)));
        ll.y = packh(__float2half_rn(v.z - __half2float(hz)),
                     __float2half_rn(v.w - __half2float(hw)));
        *reinterpret_cast<uint2*>(Ah + rr * APH + c4 * 4) = hh;
        *reinterpret_cast<uint2*>(Al + rr * APH + c4 * 4) = ll;
    }

    float c[2][8][4];

    for (int l = 0; l < 3; l++) {
        if (tid < 256) {
            biasS[tid] = (l == 0 ? b1 : (l == 1 ? b2 : b3))[e * 256 + tid];
            if (l < 2) {
                gamS[tid] = (l == 0 ? g1 : g2)[e * 256 + tid];
                betS[tid] = (l == 0 ? be1 : be2)[e * 256 + tid];
            }
        }
        __syncthreads();

        gemm_core(g_wpack + (size_t)(1 + e * 3 + l) * SLABQ, Ah, Al, Bs,
                  c, wm, wn, lane, tid);

        if (l < 2) {
            float s1[2][2] = {{0.f, 0.f}, {0.f, 0.f}};
            float s2[2][2] = {{0.f, 0.f}, {0.f, 0.f}};
#pragma unroll
            for (int m = 0; m < 2; m++)
#pragma unroll
                for (int t = 0; t < 8; t++) {
                    int colb = wn * 64 + t * 8 + tg * 2;
#pragma unroll
                    for (int h = 0; h < 2; h++)
#pragma unroll
                        for (int q = 0; q < 2; q++) {
                            float v = c[m][t][h * 2 + q] + biasS[colb + q];
                            c[m][t][h * 2 + q] = v;
                            s1[m][h] += v; s2[m][h] += v * v;
                        }
                }
#pragma unroll
            for (int off = 1; off <= 2; off <<= 1)
#pragma unroll
                for (int m = 0; m < 2; m++)
#pragma unroll
                    for (int h = 0; h < 2; h++) {
                        s1[m][h] += __shfl_xor_sync(0xffffffffu, s1[m][h], off);
                        s2[m][h] += __shfl_xor_sync(0xffffffffu, s2[m][h], off);
                    }
            if (tg == 0) {
#pragma unroll
                for (int m = 0; m < 2; m++)
#pragma unroll
                    for (int h = 0; h < 2; h++) {
                        int row = wm * 32 + m * 16 + g + h * 8;
                        redS[wn][row][0] = s1[m][h];
                        redS[wn][row][1] = s2[m][h];
                    }
            }
            __syncthreads();
            if (tid < BM) {
                float a = redS[0][tid][0] + redS[1][tid][0] + redS[2][tid][0] + redS[3][tid][0];
                float b = redS[0][tid][1] + redS[1][tid][1] + redS[2][tid][1] + redS[3][tid][1];
                float mean = a * (1.f / 256.f);
                float var  = b * (1.f / 256.f) - mean * mean;
                mrS[tid][0] = mean;
                mrS[tid][1] = rsqrtf(var + 1e-5f);
            }
            __syncthreads();
            // normalize + relu + fp16 split -> Ah/Al (next layer A)
#pragma unroll
            for (int m = 0; m < 2; m++)
#pragma unroll
                for (int h = 0; h < 2; h++) {
                    int row = wm * 32 + m * 16 + g + h * 8;
                    float mean = mrS[row][0], rs = mrS[row][1];
#pragma unroll
                    for (int t = 0; t < 8; t++) {
                        int colb = wn * 64 + t * 8 + tg * 2;
                        float h0 = fmaxf((c[m][t][h * 2 + 0] - mean) * rs * gamS[colb]
                                         + betS[colb], 0.f);
                        float h1 = fmaxf((c[m][t][h * 2 + 1] - mean) * rs * gamS[colb + 1]
                                         + betS[colb + 1], 0.f);
                        __half hi0 = __float2half_rn(h0);
                        __half hi1 = __float2half_rn(h1);
                        __half lo0 = __float2half_rn(h0 - __half2float(hi0));
                        __half lo1 = __float2half_rn(h1 - __half2float(hi1));
                        *reinterpret_cast<uint32_t*>(Ah + row * APH + colb) = packh(hi0, hi1);
                        *reinterpret_cast<uint32_t*>(Al + row * APH + colb) = packh(lo0, lo1);
                    }
                }
            __syncthreads();
        }
    }

    // final: +b3, gate weight, store rows to g_eout[dst]
#pragma unroll
    for (int m = 0; m < 2; m++)
#pragma unroll
        for (int h = 0; h < 2; h++) {
            int row = wm * 32 + m * 16 + g + h * 8;
            if (row < mrows) {
                float wgt = wS[row];
                float* orow = g_eout + (size_t)dstS[row] * 256;
#pragma unroll
                for (int t = 0; t < 8; t++) {
                    int colb = wn * 64 + t * 8 + tg * 2;
                    float2 v = make_float2(
                        wgt * (c[m][t][h * 2 + 0] + biasS[colb]),
                        wgt * (c[m][t][h * 2 + 1] + biasS[colb + 1]));
                    *reinterpret_cast<float2*>(orow + colb) = v;
                }
            }
        }
}

// ---------------------------------------------------------------------------
__global__ void combine_kernel(float* __restrict__ out)
{
    int i = blockIdx.x * blockDim.x + threadIdx.x;   // CB*64 float4s
    if (i >= CB * 64) return;
    int t = i >> 6, c4 = i & 63;
    const float4* e4 = reinterpret_cast<const float4*>(g_eout);
    float4 a = e4[(size_t)(2 * t) * 64 + c4];
    float4 b = e4[(size_t)(2 * t + 1) * 64 + c4];
    reinterpret_cast<float4*>(out)[i] =
        make_float4(a.x + b.x, a.y + b.y, a.z + b.z, a.w + b.w);
}

// ---------------------------------------------------------------------------
extern "C" void kernel_launch(void* const* d_in, const int* in_sizes, int n_in,
                              void* d_out, int out_size)
{
    const float* x   = (const float*)d_in[0];
    const float* gw1 = (const float*)d_in[1];
    const float* gb1 = (const float*)d_in[2];
    const float* gw2 = (const float*)d_in[3];
    const float* gb2 = (const float*)d_in[4];
    const float* w1  = (const float*)d_in[5];
    const float* b1  = (const float*)d_in[6];
    const float* g1  = (const float*)d_in[7];
    const float* be1 = (const float*)d_in[8];
    const float* w2  = (const float*)d_in[9];
    const float* b2  = (const float*)d_in[10];
    const float* g2  = (const float*)d_in[11];
    const float* be2 = (const float*)d_in[12];
    const float* w3  = (const float*)d_in[13];
    const float* b3  = (const float*)d_in[14];
    float* out = (float*)d_out;

    cudaFuncSetAttribute(gating_kernel,
                         cudaFuncAttributeMaxDynamicSharedMemorySize, SMEM_GAT);
    cudaFuncSetAttribute(expert_kernel,
                         cudaFuncAttributeMaxDynamicSharedMemorySize, SMEM_EXP);

    prep_kernel<<<dim3(64, 25), 256>>>(gw1, w1, w2, w3);

    gating_kernel<<<CB / BM, NT, SMEM_GAT>>>(x, gb1, gw2, gb2);

    fixup_kernel<<<64, 256>>>(x, gw1, gb1, gw2, gb2);

    route_kernel<<<CB / 256, 256>>>();

    dim3 egrid(CB / BM, CE);
    expert_kernel<<<egrid, NT, SMEM_EXP>>>(x, b1, g1, be1, b2, g2, be2, b3);

    combine_kernel<<<(CB * 64 + 255) / 256, 256>>>(out);
}

// round 8
// speedup vs baseline: 2.4760x; 1.1787x over previous
#include <cuda_runtime.h>
#include <cuda_fp16.h>
#include <cstdint>
#include <math.h>

#define CB 32768
#define CE 8
constexpr int NT   = 512;     // threads per block (16 warps)
constexpr int BM   = 128;     // token rows per tile
constexpr int APH  = 264;     // A row stride in fp16 units (conflict-free pad)
constexpr int SLABQ = 16384;  // uint4 per packed 256x256 slab
constexpr int CHQ   = 2048;   // uint4 per K=32 chunk
constexpr int NBUF  = 2;      // B buffers

// dynamic smem layouts (bytes)
constexpr int B_BYTES   = NBUF * CHQ * 16;          // 65536
constexpr int A1_BYTES  = BM * APH * 2;             // 67584  (Ah only)
constexpr int A2_BYTES  = 2 * BM * APH * 2;         // 135168 (Ah+Al)
constexpr int SMEM_EXP  = A1_BYTES + B_BYTES;       // 133120
constexpr int SMEM_GAT  = A2_BYTES + B_BYTES
                        + 2048 * 4 + 256 * 4 + 4 * BM * 8 * 4;   // 226304

// ---------------------------------------------------------------------------
// Device scratch (static, graph-capturable)
// ---------------------------------------------------------------------------
__device__ int   g_counts[CE];
__device__ int   g_nfix;
__device__ int   g_fixlist[CB];
__device__ int   g_sel[CB];            // i0 | (i1<<8)
__device__ float g_w0[CB];
__device__ int   g_rtok[CE * CB];
__device__ float g_rw[CE * CB];
__device__ int   g_rdst[CE * CB];
__device__ uint4 g_wpack[25 * SLABQ];  // fragment-packed fp16 hi/lo weights
__device__ float g_eout[2 * CB * 256];

// ---------------------------------------------------------------------------
__device__ __forceinline__ unsigned packh(__half a, __half b) {
    return (unsigned)__half_as_ushort(a) | ((unsigned)__half_as_ushort(b) << 16);
}

__device__ __forceinline__ void mma_f16(float (&c)[4], const uint32_t (&a)[4],
                                        uint32_t b0, uint32_t b1) {
    asm volatile(
        "mma.sync.aligned.m16n8k16.row.col.f32.f16.f16.f32 "
        "{%0,%1,%2,%3}, {%4,%5,%6,%7}, {%8,%9}, {%0,%1,%2,%3};"
        : "+f"(c[0]), "+f"(c[1]), "+f"(c[2]), "+f"(c[3])
        : "r"(a[0]), "r"(a[1]), "r"(a[2]), "r"(a[3]), "r"(b0), "r"(b1));
}

// Stage one K=32 chunk (2048 uint4 = 32KB) into bs.
__device__ __forceinline__ void prefetch_chunk(const uint4* __restrict__ Wp, int cc,
                                               uint4* bs, int tid) {
    unsigned dst = (unsigned)__cvta_generic_to_shared(bs);
    const uint4* src = Wp + cc * CHQ;
#pragma unroll
    for (int i = 0; i < 4; i++) {
        int idx = i * NT + tid;
        asm volatile("cp.async.cg.shared.global [%0], [%1], 16;"
                     :: "r"(dst + idx * 16), "l"(src + idx));
    }
    asm volatile("cp.async.commit_group;");
}

// ---------------------------------------------------------------------------
// 128x256x256 GEMM, m16n8k16, templated on term count:
//   TERMS==3 (gating): ah*bh + ah*bl + al*bh   (needs Al plane)
//   TERMS==2 (expert): ah*bh + ah*bl = ah*(b exact)  (Ah only; Al unused)
// B fragments pre-packed: uint4 {bh0,bh1,bl0,bl1} at index st*1024 + nt*32 + lane,
//   k0 = st*16 + (lane&3)*2 (+1,+8,+9), n = nt*8 + (lane>>2).
// Buffer protocol per chunk cc: wait_group 0 -> barrier -> prefetch cc+1 ->
// consume cc -> barrier. Safe with NBUF=2, overlapped.
// ---------------------------------------------------------------------------
template <int TERMS>
__device__ __forceinline__ void gemm_core(const uint4* __restrict__ Wp,
                                          const __half* __restrict__ Ah,
                                          const __half* __restrict__ Al,
                                          uint4* Bs, float (&c)[2][8][4],
                                          int wm, int wn, int lane, int tid)
{
    int g  = lane >> 2;
    int tg = lane & 3;
#pragma unroll
    for (int m = 0; m < 2; m++)
#pragma unroll
        for (int t = 0; t < 8; t++)
#pragma unroll
            for (int k = 0; k < 4; k++) c[m][t][k] = 0.f;

    prefetch_chunk(Wp, 0, Bs, tid);

    for (int cc = 0; cc < 8; cc++) {
        asm volatile("cp.async.wait_group 0;" ::: "memory");
        __syncthreads();
        if (cc < 7)
            prefetch_chunk(Wp, cc + 1, Bs + ((cc + 1) & 1) * CHQ, tid);

        const uint4* bb = Bs + (cc & 1) * CHQ;
#pragma unroll
        for (int s = 0; s < 2; s++) {
            int kb = cc * 32 + s * 16;
            uint32_t ah_[2][4], al_[2][4];
#pragma unroll
            for (int m = 0; m < 2; m++) {
                const __half* pa = Ah + (wm * 32 + m * 16 + g) * APH + kb + tg * 2;
                ah_[m][0] = *reinterpret_cast<const uint32_t*>(pa);
                ah_[m][1] = *reinterpret_cast<const uint32_t*>(pa + 8 * APH);
                ah_[m][2] = *reinterpret_cast<const uint32_t*>(pa + 8);
                ah_[m][3] = *reinterpret_cast<const uint32_t*>(pa + 8 * APH + 8);
                if (TERMS == 3) {
                    const __half* pl = Al + (wm * 32 + m * 16 + g) * APH + kb + tg * 2;
                    al_[m][0] = *reinterpret_cast<const uint32_t*>(pl);
                    al_[m][1] = *reinterpret_cast<const uint32_t*>(pl + 8 * APH);
                    al_[m][2] = *reinterpret_cast<const uint32_t*>(pl + 8);
                    al_[m][3] = *reinterpret_cast<const uint32_t*>(pl + 8 * APH + 8);
                }
            }
            const uint4* bp = bb + s * 1024 + wn * 256 + lane;
#pragma unroll
            for (int t = 0; t < 8; t++) {
                uint4 bv = bp[t * 32];
#pragma unroll
                for (int m = 0; m < 2; m++) {
                    mma_f16(c[m][t], ah_[m], bv.x, bv.y);       // ah*bh
                    mma_f16(c[m][t], ah_[m], bv.z, bv.w);       // ah*bl
                    if (TERMS == 3)
                        mma_f16(c[m][t], al_[m], bv.x, bv.y);   // al*bh
                }
            }
        }
        __syncthreads();   // all reads of buf cc done before it is refilled
    }
}

// ---------------------------------------------------------------------------
// prep: zero counters; pack 25 slabs into fp16 hi/lo fragment uint4s.
// ---------------------------------------------------------------------------
__global__ void prep_kernel(const float* __restrict__ gw1,
                            const float* __restrict__ w1,
                            const float* __restrict__ w2,
                            const float* __restrict__ w3)
{
    int tid = threadIdx.x;
    if (blockIdx.x == 0 && blockIdx.y == 0) {
        if (tid < CE) g_counts[tid] = 0;
        if (tid == CE) g_nfix = 0;
    }
    int slab = blockIdx.y;
    const float* src;
    if (slab == 0) src = gw1;
    else {
        int e = (slab - 1) / 3, l = (slab - 1) % 3;
        src = (l == 0 ? w1 : (l == 1 ? w2 : w3)) + (size_t)e * 65536;
    }
    int idx  = blockIdx.x * 256 + tid;     // 0..16383
    int lane = idx & 31;
    int nt   = (idx >> 5) & 31;
    int st   = idx >> 10;                  // 0..15
    int k0 = st * 16 + (lane & 3) * 2;
    int n  = nt * 8 + (lane >> 2);

    float v00 = src[(size_t)k0 * 256 + n];
    float v01 = src[(size_t)(k0 + 1) * 256 + n];
    float v10 = src[(size_t)(k0 + 8) * 256 + n];
    float v11 = src[(size_t)(k0 + 9) * 256 + n];
    __half h00 = __float2half_rn(v00), h01 = __float2half_rn(v01);
    __half h10 = __float2half_rn(v10), h11 = __float2half_rn(v11);
    __half l00 = __float2half_rn(v00 - __half2float(h00));
    __half l01 = __float2half_rn(v01 - __half2float(h01));
    __half l10 = __float2half_rn(v10 - __half2float(h10));
    __half l11 = __float2half_rn(v11 - __half2float(h11));
    uint4 o;
    o.x = packh(h00, h01); o.y = packh(h10, h11);
    o.z = packh(l00, l01); o.w = packh(l10, l11);
    g_wpack[(size_t)slab * SLABQ + idx] = o;
}

// ---------------------------------------------------------------------------
// Gating: 3-term fp16-split GEMM1 -> relu(+gb1) -> fp32 logits -> top-2;
// near-tie tokens flagged for exact fp32 fixup.
// ---------------------------------------------------------------------------
__global__ void __launch_bounds__(NT, 1)
gating_kernel(const float* __restrict__ x,
              const float* __restrict__ gb1,
              const float* __restrict__ gw2,
              const float* __restrict__ gb2)
{
    extern __shared__ char smraw[];
    __half* Ah   = (__half*)smraw;
    __half* Al   = Ah + BM * APH;
    uint4*  Bs   = (uint4*)(smraw + A2_BYTES);
    float*  gw2s = (float*)(smraw + A2_BYTES + B_BYTES);  // 2048
    float*  gb1s = gw2s + 2048;                           // 256
    float (*lgS)[BM][8] = (float (*)[BM][8])(gb1s + 256); // [4][BM][8]

    int tid  = threadIdx.x;
    int wid  = tid >> 5;
    int lane = tid & 31;
    int wm = wid >> 2, wn = wid & 3;
    int g = lane >> 2, tg = lane & 3;
    int t0 = blockIdx.x * BM;

    for (int i = tid; i < 2048; i += NT) gw2s[i] = gw2[i];
    if (tid < 256) gb1s[tid] = gb1[tid];

    // A = x rows, fp16 hi/lo split
    const float4* x4 = reinterpret_cast<const float4*>(x);
    for (int i = tid; i < BM * 64; i += NT) {
        int rr = i >> 6, c4 = i & 63;
        float4 v = __ldg(&x4[(size_t)(t0 + rr) * 64 + c4]);
        __half hx = __float2half_rn(v.x), hy = __float2half_rn(v.y);
        __half hz = __float2half_rn(v.z), hw = __float2half_rn(v.w);
        uint2 hh, ll;
        hh.x = packh(hx, hy); hh.y = packh(hz, hw);
        ll.x = packh(__float2half_rn(v.x - __half2float(hx)),
                     __float2half_rn(v.y - __half2float(hy)));
        ll.y = packh(__float2half_rn(v.z - __half2float(hz)),
                     __float2half_rn(v.w - __half2float(hw)));
        *reinterpret_cast<uint2*>(Ah + rr * APH + c4 * 4) = hh;
        *reinterpret_cast<uint2*>(Al + rr * APH + c4 * 4) = ll;
    }
    __syncthreads();

    float c[2][8][4];
    gemm_core<3>(g_wpack, Ah, Al, Bs, c, wm, wn, lane, tid);

    // logits partials (fp32)
    float lg[2][2][8];
#pragma unroll
    for (int m = 0; m < 2; m++)
#pragma unroll
        for (int h = 0; h < 2; h++)
#pragma unroll
            for (int e = 0; e < 8; e++) lg[m][h][e] = 0.f;

#pragma unroll
    for (int m = 0; m < 2; m++)
#pragma unroll
        for (int t = 0; t < 8; t++) {
            int colb = wn * 64 + t * 8 + tg * 2;
#pragma unroll
            for (int h = 0; h < 2; h++)
#pragma unroll
                for (int q = 0; q < 2; q++) {
                    int col = colb + q;
                    float hv = fmaxf(c[m][t][h * 2 + q] + gb1s[col], 0.f);
                    const float4* gp = reinterpret_cast<const float4*>(gw2s + col * 8);
                    float4 p0 = gp[0], p1 = gp[1];
                    lg[m][h][0] += hv * p0.x; lg[m][h][1] += hv * p0.y;
                    lg[m][h][2] += hv * p0.z; lg[m][h][3] += hv * p0.w;
                    lg[m][h][4] += hv * p1.x; lg[m][h][5] += hv * p1.y;
                    lg[m][h][6] += hv * p1.z; lg[m][h][7] += hv * p1.w;
                }
        }
#pragma unroll
    for (int off = 1; off <= 2; off <<= 1)
#pragma unroll
        for (int m = 0; m < 2; m++)
#pragma unroll
            for (int h = 0; h < 2; h++)
#pragma unroll
                for (int e = 0; e < 8; e++)
                    lg[m][h][e] += __shfl_xor_sync(0xffffffffu, lg[m][h][e], off);
    if (tg == 0) {
#pragma unroll
        for (int m = 0; m < 2; m++)
#pragma unroll
            for (int h = 0; h < 2; h++) {
                int row = wm * 32 + m * 16 + g + h * 8;
#pragma unroll
                for (int e = 0; e < 8; e++) lgS[wn][row][e] = lg[m][h][e];
            }
    }
    __syncthreads();

    if (tid < BM) {
        float l[CE];
#pragma unroll
        for (int e = 0; e < CE; e++)
            l[e] = lgS[0][tid][e] + lgS[1][tid][e] + lgS[2][tid][e] + lgS[3][tid][e]
                 + __ldg(&gb2[e]);
        int i0 = 0;
#pragma unroll
        for (int e = 1; e < CE; e++) if (l[e] > l[i0]) i0 = e;
        int i1 = (i0 == 0) ? 1 : 0;
#pragma unroll
        for (int e = 0; e < CE; e++) if (e != i0 && l[e] > l[i1]) i1 = e;
        float l2v = -1e30f;
#pragma unroll
        for (int e = 0; e < CE; e++)
            if (e != i0 && e != i1 && l[e] > l2v) l2v = l[e];
        float w0 = 1.f / (1.f + expf(l[i1] - l[i0]));
        int tok = t0 + tid;
        g_sel[tok] = i0 | (i1 << 8);
        g_w0[tok]  = w0;
        if (l[i1] - l2v < 1e-4f) {
            int p = atomicAdd(&g_nfix, 1);
            g_fixlist[p] = tok;
        }
    }
}

// ---------------------------------------------------------------------------
// Exact-fp32 gating recompute for flagged near-tie tokens.
// ---------------------------------------------------------------------------
__global__ void fixup_kernel(const float* __restrict__ x,
                             const float* __restrict__ gw1,
                             const float* __restrict__ gb1,
                             const float* __restrict__ gw2,
                             const float* __restrict__ gb2)
{
    __shared__ float hS[256];
    __shared__ float lg8[CE];
    int nf = g_nfix;
    int tid = threadIdx.x;
    for (int i = blockIdx.x; i < nf; i += gridDim.x) {
        int t = g_fixlist[i];
        const float* xr = x + (size_t)t * 256;
        float acc = 0.f;
        for (int k = 0; k < 256; k++)
            acc = fmaf(__ldg(&xr[k]), __ldg(&gw1[(size_t)k * 256 + tid]), acc);
        hS[tid] = fmaxf(acc + __ldg(&gb1[tid]), 0.f);
        __syncthreads();
        int wid = tid >> 5, lane = tid & 31;
        float s = 0.f;
        for (int j = lane; j < 256; j += 32) s += hS[j] * __ldg(&gw2[j * 8 + wid]);
#pragma unroll
        for (int o = 16; o > 0; o >>= 1) s += __shfl_xor_sync(0xffffffffu, s, o);
        if (lane == 0) lg8[wid] = s + __ldg(&gb2[wid]);
        __syncthreads();
        if (tid == 0) {
            float l[CE];
#pragma unroll
            for (int e = 0; e < CE; e++) l[e] = lg8[e];
            int i0 = 0;
#pragma unroll
            for (int e = 1; e < CE; e++) if (l[e] > l[i0]) i0 = e;
            int i1 = (i0 == 0) ? 1 : 0;
#pragma unroll
            for (int e = 0; e < CE; e++) if (e != i0 && l[e] > l[i1]) i1 = e;
            g_sel[t] = i0 | (i1 << 8);
            g_w0[t]  = 1.f / (1.f + expf(l[i1] - l[i0]));
        }
        __syncthreads();
    }
}

// ---------------------------------------------------------------------------
__global__ void route_kernel()
{
    __shared__ int cnt[CE], baseI[CE];
    int tid = threadIdx.x;
    int t = blockIdx.x * 256 + tid;
    if (tid < CE) cnt[tid] = 0;
    __syncthreads();
    int sel = g_sel[t];
    int e0 = sel & 255, e1 = sel >> 8;
    float w0 = g_w0[t];
    int p0 = atomicAdd(&cnt[e0], 1);
    int p1 = atomicAdd(&cnt[e1], 1);
    __syncthreads();
    if (tid < CE) baseI[tid] = atomicAdd(&g_counts[tid], cnt[tid]);
    __syncthreads();
    int q0 = e0 * CB + baseI[e0] + p0;
    g_rtok[q0] = t; g_rw[q0] = w0;        g_rdst[q0] = 2 * t;
    int q1 = e1 * CB + baseI[e1] + p1;
    g_rtok[q1] = t; g_rw[q1] = 1.f - w0;  g_rdst[q1] = 2 * t + 1;
}

// ---------------------------------------------------------------------------
// Expert kernel: fused 3-layer MLP on routed 128-token tiles; 2-term GEMMs
// (A single fp16 plane, B exact via hi/lo); LN in registers; rows to g_eout.
// ---------------------------------------------------------------------------
__global__ void __launch_bounds__(NT, 1)
expert_kernel(const float* __restrict__ x,
              const float* __restrict__ b1, const float* __restrict__ g1,
              const float* __restrict__ be1,
              const float* __restrict__ b2, const float* __restrict__ g2,
              const float* __restrict__ be2,
              const float* __restrict__ b3)
{
    int e = blockIdx.y;
    int count = g_counts[e];
    int t0 = blockIdx.x * BM;
    if (t0 >= count) return;
    int mrows = min(BM, count - t0);

    extern __shared__ char smraw[];
    __half* Ah = (__half*)smraw;
    uint4*  Bs = (uint4*)(smraw + A1_BYTES);

    __shared__ int   tokS[BM];
    __shared__ float wS[BM];
    __shared__ int   dstS[BM];
    __shared__ float biasS[256], gamS[256], betS[256];
    __shared__ float redS[4][BM][2];
    __shared__ float mrS[BM][2];

    int tid  = threadIdx.x;
    int wid  = tid >> 5;
    int lane = tid & 31;
    int wm = wid >> 2, wn = wid & 3;
    int g = lane >> 2, tg = lane & 3;

    if (tid < BM) {
        bool v = tid < mrows;
        int q = e * CB + t0 + tid;
        tokS[tid] = v ? g_rtok[q] : 0;
        wS[tid]   = v ? g_rw[q]   : 0.f;
        dstS[tid] = v ? g_rdst[q] : 0;
    }
    __syncthreads();

    // A = gathered x rows, fp16 (hi only; al term dropped by design)
    const float4* x4 = reinterpret_cast<const float4*>(x);
    for (int i = tid; i < BM * 64; i += NT) {
        int rr = i >> 6, c4 = i & 63;
        float4 v = __ldg(&x4[(size_t)tokS[rr] * 64 + c4]);
        uint2 hh;
        hh.x = packh(__float2half_rn(v.x), __float2half_rn(v.y));
        hh.y = packh(__float2half_rn(v.z), __float2half_rn(v.w));
        *reinterpret_cast<uint2*>(Ah + rr * APH + c4 * 4) = hh;
    }

    float c[2][8][4];

    for (int l = 0; l < 3; l++) {
        if (tid < 256) {
            biasS[tid] = (l == 0 ? b1 : (l == 1 ? b2 : b3))[e * 256 + tid];
            if (l < 2) {
                gamS[tid] = (l == 0 ? g1 : g2)[e * 256 + tid];
                betS[tid] = (l == 0 ? be1 : be2)[e * 256 + tid];
            }
        }
        __syncthreads();

        gemm_core<2>(g_wpack + (size_t)(1 + e * 3 + l) * SLABQ, Ah, Ah, Bs,
                     c, wm, wn, lane, tid);

        if (l < 2) {
            float s1[2][2] = {{0.f, 0.f}, {0.f, 0.f}};
            float s2[2][2] = {{0.f, 0.f}, {0.f, 0.f}};
#pragma unroll
            for (int m = 0; m < 2; m++)
#pragma unroll
                for (int t = 0; t < 8; t++) {
                    int colb = wn * 64 + t * 8 + tg * 2;
#pragma unroll
                    for (int h = 0; h < 2; h++)
#pragma unroll
                        for (int q = 0; q < 2; q++) {
                            float v = c[m][t][h * 2 + q] + biasS[colb + q];
                            c[m][t][h * 2 + q] = v;
                            s1[m][h] += v; s2[m][h] += v * v;
                        }
                }
#pragma unroll
            for (int off = 1; off <= 2; off <<= 1)
#pragma unroll
                for (int m = 0; m < 2; m++)
#pragma unroll
                    for (int h = 0; h < 2; h++) {
                        s1[m][h] += __shfl_xor_sync(0xffffffffu, s1[m][h], off);
                        s2[m][h] += __shfl_xor_sync(0xffffffffu, s2[m][h], off);
                    }
            if (tg == 0) {
#pragma unroll
                for (int m = 0; m < 2; m++)
#pragma unroll
                    for (int h = 0; h < 2; h++) {
                        int row = wm * 32 + m * 16 + g + h * 8;
                        redS[wn][row][0] = s1[m][h];
                        redS[wn][row][1] = s2[m][h];
                    }
            }
            __syncthreads();
            if (tid < BM) {
                float a = redS[0][tid][0] + redS[1][tid][0] + redS[2][tid][0] + redS[3][tid][0];
                float b = redS[0][tid][1] + redS[1][tid][1] + redS[2][tid][1] + redS[3][tid][1];
                float mean = a * (1.f / 256.f);
                float var  = b * (1.f / 256.f) - mean * mean;
                mrS[tid][0] = mean;
                mrS[tid][1] = rsqrtf(var + 1e-5f);
            }
            __syncthreads();
            // normalize + relu + fp16 round -> Ah (next layer A)
#pragma unroll
            for (int m = 0; m < 2; m++)
#pragma unroll
                for (int h = 0; h < 2; h++) {
                    int row = wm * 32 + m * 16 + g + h * 8;
                    float mean = mrS[row][0], rs = mrS[row][1];
#pragma unroll
                    for (int t = 0; t < 8; t++) {
                        int colb = wn * 64 + t * 8 + tg * 2;
                        float h0 = fmaxf((c[m][t][h * 2 + 0] - mean) * rs * gamS[colb]
                                         + betS[colb], 0.f);
                        float h1 = fmaxf((c[m][t][h * 2 + 1] - mean) * rs * gamS[colb + 1]
                                         + betS[colb + 1], 0.f);
                        *reinterpret_cast<uint32_t*>(Ah + row * APH + colb) =
                            packh(__float2half_rn(h0), __float2half_rn(h1));
                    }
                }
            __syncthreads();
        }
    }

    // final: +b3, gate weight, store rows to g_eout[dst]
#pragma unroll
    for (int m = 0; m < 2; m++)
#pragma unroll
        for (int h = 0; h < 2; h++) {
            int row = wm * 32 + m * 16 + g + h * 8;
            if (row < mrows) {
                float wgt = wS[row];
                float* orow = g_eout + (size_t)dstS[row] * 256;
#pragma unroll
                for (int t = 0; t < 8; t++) {
                    int colb = wn * 64 + t * 8 + tg * 2;
                    float2 v = make_float2(
                        wgt * (c[m][t][h * 2 + 0] + biasS[colb]),
                        wgt * (c[m][t][h * 2 + 1] + biasS[colb + 1]));
                    *reinterpret_cast<float2*>(orow + colb) = v;
                }
            }
        }
}

// ---------------------------------------------------------------------------
__global__ void combine_kernel(float* __restrict__ out)
{
    int i = blockIdx.x * blockDim.x + threadIdx.x;   // CB*64 float4s
    if (i >= CB * 64) return;
    int t = i >> 6, c4 = i & 63;
    const float4* e4 = reinterpret_cast<const float4*>(g_eout);
    float4 a = e4[(size_t)(2 * t) * 64 + c4];
    float4 b = e4[(size_t)(2 * t + 1) * 64 + c4];
    reinterpret_cast<float4*>(out)[i] =
        make_float4(a.x + b.x, a.y + b.y, a.z + b.z, a.w + b.w);
}

// ---------------------------------------------------------------------------
extern "C" void kernel_launch(void* const* d_in, const int* in_sizes, int n_in,
                              void* d_out, int out_size)
{
    const float* x   = (const float*)d_in[0];
    const float* gw1 = (const float*)d_in[1];
    const float* gb1 = (const float*)d_in[2];
    const float* gw2 = (const float*)d_in[3];
    const float* gb2 = (const float*)d_in[4];
    const float* w1  = (const float*)d_in[5];
    const float* b1  = (const float*)d_in[6];
    const float* g1  = (const float*)d_in[7];
    const float* be1 = (const float*)d_in[8];
    const float* w2  = (const float*)d_in[9];
    const float* b2  = (const float*)d_in[10];
    const float* g2  = (const float*)d_in[11];
    const float* be2 = (const float*)d_in[12];
    const float* w3  = (const float*)d_in[13];
    const float* b3  = (const float*)d_in[14];
    float* out = (float*)d_out;

    cudaFuncSetAttribute(gating_kernel,
                         cudaFuncAttributeMaxDynamicSharedMemorySize, SMEM_GAT);
    cudaFuncSetAttribute(expert_kernel,
                         cudaFuncAttributeMaxDynamicSharedMemorySize, SMEM_EXP);

    prep_kernel<<<dim3(64, 25), 256>>>(gw1, w1, w2, w3);

    gating_kernel<<<CB / BM, NT, SMEM_GAT>>>(x, gb1, gw2, gb2);

    fixup_kernel<<<64, 256>>>(x, gw1, gb1, gw2, gb2);

    route_kernel<<<CB / 256, 256>>>();

    dim3 egrid(CB / BM, CE);
    expert_kernel<<<egrid, NT, SMEM_EXP>>>(x, b1, g1, be1, b2, g2, be2, b3);

    combine_kernel<<<(CB * 64 + 255) / 256, 256>>>(out);
}

// round 9
// speedup vs baseline: 2.6952x; 1.0886x over previous
#include <cuda_runtime.h>
#include <cuda_fp16.h>
#include <cstdint>
#include <math.h>

#define CB 32768
#define CE 8
constexpr int NT   = 512;     // threads per block (16 warps)
constexpr int BM   = 128;     // token rows per tile
constexpr int APH  = 264;     // A row stride in fp16 units (conflict-free pad)
constexpr int SLABQ = 16384;  // uint4 per packed 256x256 slab
constexpr int CHQ   = 4096;   // uint4 per K=64 chunk (64KB)
constexpr int NBUF  = 2;      // B buffers

// dynamic smem layouts (bytes)
constexpr int B_BYTES   = NBUF * CHQ * 16;          // 131072
constexpr int A1_BYTES  = BM * APH * 2;             // 67584  (Ah only)
constexpr int SMEM_EXP  = A1_BYTES + B_BYTES;       // 198656
constexpr int SMEM_GAT  = SMEM_EXP
                        + 2048 * 4 + 256 * 4 + 4 * BM * 8 * 4;   // 224256

// ---------------------------------------------------------------------------
// Device scratch (static, graph-capturable)
// ---------------------------------------------------------------------------
__device__ int   g_counts[CE];
__device__ int   g_nfix;
__device__ int   g_fixlist[CB];
__device__ int   g_sel[CB];            // i0 | (i1<<8)
__device__ float g_w0[CB];
__device__ int   g_rtok[CE * CB];
__device__ float g_rw[CE * CB];
__device__ int   g_rdst[CE * CB];
__device__ uint4 g_wpack[25 * SLABQ];  // fragment-packed fp16 hi/lo weights
__device__ float g_eout[2 * CB * 256];

// ---------------------------------------------------------------------------
__device__ __forceinline__ unsigned packh(__half a, __half b) {
    return (unsigned)__half_as_ushort(a) | ((unsigned)__half_as_ushort(b) << 16);
}

__device__ __forceinline__ void mma_f16(float (&c)[4], const uint32_t (&a)[4],
                                        uint32_t b0, uint32_t b1) {
    asm volatile(
        "mma.sync.aligned.m16n8k16.row.col.f32.f16.f16.f32 "
        "{%0,%1,%2,%3}, {%4,%5,%6,%7}, {%8,%9}, {%0,%1,%2,%3};"
        : "+f"(c[0]), "+f"(c[1]), "+f"(c[2]), "+f"(c[3])
        : "r"(a[0]), "r"(a[1]), "r"(a[2]), "r"(a[3]), "r"(b0), "r"(b1));
}

// Stage one K=64 chunk (4096 uint4 = 64KB) into bs.
__device__ __forceinline__ void prefetch_chunk(const uint4* __restrict__ Wp, int cc,
                                               uint4* bs, int tid) {
    unsigned dst = (unsigned)__cvta_generic_to_shared(bs);
    const uint4* src = Wp + cc * CHQ;
#pragma unroll
    for (int i = 0; i < 8; i++) {
        int idx = i * NT + tid;
        asm volatile("cp.async.cg.shared.global [%0], [%1], 16;"
                     :: "r"(dst + idx * 16), "l"(src + idx));
    }
    asm volatile("cp.async.commit_group;");
}

// ---------------------------------------------------------------------------
// 128x256x256 GEMM, m16n8k16, 2-term fp16 split: ah*bh + ah*bl = ah*(b exact).
// Only error source: rounding A to fp16 (validated model: ~1.2e-4 per GEMM).
// B fragments pre-packed: uint4 {bh0,bh1,bl0,bl1} at index st*1024 + nt*32 + lane,
//   st = global k16-step (chunk cc covers st = cc*4 .. cc*4+3),
//   k0 = st*16 + (lane&3)*2 (+1,+8,+9), n = nt*8 + (lane>>2).
// Buffer protocol per chunk cc: wait_group 0 -> barrier -> prefetch cc+1 ->
// consume cc (4 k16-steps) -> barrier. NBUF=2, overlapped, race-free.
// ---------------------------------------------------------------------------
__device__ __forceinline__ void gemm_core(const uint4* __restrict__ Wp,
                                          const __half* __restrict__ Ah,
                                          uint4* Bs, float (&c)[2][8][4],
                                          int wm, int wn, int lane, int tid)
{
    int g  = lane >> 2;
    int tg = lane & 3;
#pragma unroll
    for (int m = 0; m < 2; m++)
#pragma unroll
        for (int t = 0; t < 8; t++)
#pragma unroll
            for (int k = 0; k < 4; k++) c[m][t][k] = 0.f;

    prefetch_chunk(Wp, 0, Bs, tid);

    for (int cc = 0; cc < 4; cc++) {
        asm volatile("cp.async.wait_group 0;" ::: "memory");
        __syncthreads();
        if (cc < 3)
            prefetch_chunk(Wp, cc + 1, Bs + ((cc + 1) & 1) * CHQ, tid);

        const uint4* bb = Bs + (cc & 1) * CHQ;
#pragma unroll
        for (int s = 0; s < 4; s++) {
            int kb = cc * 64 + s * 16;
            uint32_t ah_[2][4];
#pragma unroll
            for (int m = 0; m < 2; m++) {
                const __half* pa = Ah + (wm * 32 + m * 16 + g) * APH + kb + tg * 2;
                ah_[m][0] = *reinterpret_cast<const uint32_t*>(pa);
                ah_[m][1] = *reinterpret_cast<const uint32_t*>(pa + 8 * APH);
                ah_[m][2] = *reinterpret_cast<const uint32_t*>(pa + 8);
                ah_[m][3] = *reinterpret_cast<const uint32_t*>(pa + 8 * APH + 8);
            }
            const uint4* bp = bb + s * 1024 + wn * 256 + lane;
#pragma unroll
            for (int t = 0; t < 8; t++) {
                uint4 bv = bp[t * 32];
#pragma unroll
                for (int m = 0; m < 2; m++) {
                    mma_f16(c[m][t], ah_[m], bv.x, bv.y);   // ah*bh
                    mma_f16(c[m][t], ah_[m], bv.z, bv.w);   // ah*bl
                }
            }
        }
        __syncthreads();   // all reads of buf cc done before it is refilled
    }
}

// ---------------------------------------------------------------------------
// prep: zero counters; pack 25 slabs into fp16 hi/lo fragment uint4s.
// ---------------------------------------------------------------------------
__global__ void prep_kernel(const float* __restrict__ gw1,
                            const float* __restrict__ w1,
                            const float* __restrict__ w2,
                            const float* __restrict__ w3)
{
    int tid = threadIdx.x;
    if (blockIdx.x == 0 && blockIdx.y == 0) {
        if (tid < CE) g_counts[tid] = 0;
        if (tid == CE) g_nfix = 0;
    }
    int slab = blockIdx.y;
    const float* src;
    if (slab == 0) src = gw1;
    else {
        int e = (slab - 1) / 3, l = (slab - 1) % 3;
        src = (l == 0 ? w1 : (l == 1 ? w2 : w3)) + (size_t)e * 65536;
    }
    int idx  = blockIdx.x * 256 + tid;     // 0..16383
    int lane = idx & 31;
    int nt   = (idx >> 5) & 31;
    int st   = idx >> 10;                  // 0..15
    int k0 = st * 16 + (lane & 3) * 2;
    int n  = nt * 8 + (lane >> 2);

    float v00 = src[(size_t)k0 * 256 + n];
    float v01 = src[(size_t)(k0 + 1) * 256 + n];
    float v10 = src[(size_t)(k0 + 8) * 256 + n];
    float v11 = src[(size_t)(k0 + 9) * 256 + n];
    __half h00 = __float2half_rn(v00), h01 = __float2half_rn(v01);
    __half h10 = __float2half_rn(v10), h11 = __float2half_rn(v11);
    __half l00 = __float2half_rn(v00 - __half2float(h00));
    __half l01 = __float2half_rn(v01 - __half2float(h01));
    __half l10 = __float2half_rn(v10 - __half2float(h10));
    __half l11 = __float2half_rn(v11 - __half2float(h11));
    uint4 o;
    o.x = packh(h00, h01); o.y = packh(h10, h11);
    o.z = packh(l00, l01); o.w = packh(l10, l11);
    g_wpack[(size_t)slab * SLABQ + idx] = o;
}

// ---------------------------------------------------------------------------
// Gating: 2-term fp16-split GEMM1 (B exact; logit err ~5e-6 << 1e-4 margin)
// -> relu(+gb1) -> fp32 logits -> top-2; near-ties flagged for exact fixup.
// ---------------------------------------------------------------------------
__global__ void __launch_bounds__(NT, 1)
gating_kernel(const float* __restrict__ x,
              const float* __restrict__ gb1,
              const float* __restrict__ gw2,
              const float* __restrict__ gb2)
{
    extern __shared__ char smraw[];
    __half* Ah   = (__half*)smraw;
    uint4*  Bs   = (uint4*)(smraw + A1_BYTES);
    float*  gw2s = (float*)(smraw + SMEM_EXP);            // 2048
    float*  gb1s = gw2s + 2048;                           // 256
    float (*lgS)[BM][8] = (float (*)[BM][8])(gb1s + 256); // [4][BM][8]

    int tid  = threadIdx.x;
    int wid  = tid >> 5;
    int lane = tid & 31;
    int wm = wid >> 2, wn = wid & 3;
    int g = lane >> 2, tg = lane & 3;
    int t0 = blockIdx.x * BM;

    for (int i = tid; i < 2048; i += NT) gw2s[i] = gw2[i];
    if (tid < 256) gb1s[tid] = gb1[tid];

    // A = x rows, fp16 (hi only)
    const float4* x4 = reinterpret_cast<const float4*>(x);
    for (int i = tid; i < BM * 64; i += NT) {
        int rr = i >> 6, c4 = i & 63;
        float4 v = __ldg(&x4[(size_t)(t0 + rr) * 64 + c4]);
        uint2 hh;
        hh.x = packh(__float2half_rn(v.x), __float2half_rn(v.y));
        hh.y = packh(__float2half_rn(v.z), __float2half_rn(v.w));
        *reinterpret_cast<uint2*>(Ah + rr * APH + c4 * 4) = hh;
    }
    __syncthreads();

    float c[2][8][4];
    gemm_core(g_wpack, Ah, Bs, c, wm, wn, lane, tid);

    // logits partials (fp32)
    float lg[2][2][8];
#pragma unroll
    for (int m = 0; m < 2; m++)
#pragma unroll
        for (int h = 0; h < 2; h++)
#pragma unroll
            for (int e = 0; e < 8; e++) lg[m][h][e] = 0.f;

#pragma unroll
    for (int m = 0; m < 2; m++)
#pragma unroll
        for (int t = 0; t < 8; t++) {
            int colb = wn * 64 + t * 8 + tg * 2;
#pragma unroll
            for (int h = 0; h < 2; h++)
#pragma unroll
                for (int q = 0; q < 2; q++) {
                    int col = colb + q;
                    float hv = fmaxf(c[m][t][h * 2 + q] + gb1s[col], 0.f);
                    const float4* gp = reinterpret_cast<const float4*>(gw2s + col * 8);
                    float4 p0 = gp[0], p1 = gp[1];
                    lg[m][h][0] += hv * p0.x; lg[m][h][1] += hv * p0.y;
                    lg[m][h][2] += hv * p0.z; lg[m][h][3] += hv * p0.w;
                    lg[m][h][4] += hv * p1.x; lg[m][h][5] += hv * p1.y;
                    lg[m][h][6] += hv * p1.z; lg[m][h][7] += hv * p1.w;
                }
        }
#pragma unroll
    for (int off = 1; off <= 2; off <<= 1)
#pragma unroll
        for (int m = 0; m < 2; m++)
#pragma unroll
            for (int h = 0; h < 2; h++)
#pragma unroll
                for (int e = 0; e < 8; e++)
                    lg[m][h][e] += __shfl_xor_sync(0xffffffffu, lg[m][h][e], off);
    if (tg == 0) {
#pragma unroll
        for (int m = 0; m < 2; m++)
#pragma unroll
            for (int h = 0; h < 2; h++) {
                int row = wm * 32 + m * 16 + g + h * 8;
#pragma unroll
                for (int e = 0; e < 8; e++) lgS[wn][row][e] = lg[m][h][e];
            }
    }
    __syncthreads();

    if (tid < BM) {
        float l[CE];
#pragma unroll
        for (int e = 0; e < CE; e++)
            l[e] = lgS[0][tid][e] + lgS[1][tid][e] + lgS[2][tid][e] + lgS[3][tid][e]
                 + __ldg(&gb2[e]);
        int i0 = 0;
#pragma unroll
        for (int e = 1; e < CE; e++) if (l[e] > l[i0]) i0 = e;
        int i1 = (i0 == 0) ? 1 : 0;
#pragma unroll
        for (int e = 0; e < CE; e++) if (e != i0 && l[e] > l[i1]) i1 = e;
        float l2v = -1e30f;
#pragma unroll
        for (int e = 0; e < CE; e++)
            if (e != i0 && e != i1 && l[e] > l2v) l2v = l[e];
        float w0 = 1.f / (1.f + expf(l[i1] - l[i0]));
        int tok = t0 + tid;
        g_sel[tok] = i0 | (i1 << 8);
        g_w0[tok]  = w0;
        if (l[i1] - l2v < 1e-4f) {
            int p = atomicAdd(&g_nfix, 1);
            g_fixlist[p] = tok;
        }
    }
}

// ---------------------------------------------------------------------------
// Exact-fp32 gating recompute for flagged near-tie tokens.
// ---------------------------------------------------------------------------
__global__ void fixup_kernel(const float* __restrict__ x,
                             const float* __restrict__ gw1,
                             const float* __restrict__ gb1,
                             const float* __restrict__ gw2,
                             const float* __restrict__ gb2)
{
    __shared__ float hS[256];
    __shared__ float lg8[CE];
    int nf = g_nfix;
    int tid = threadIdx.x;
    for (int i = blockIdx.x; i < nf; i += gridDim.x) {
        int t = g_fixlist[i];
        const float* xr = x + (size_t)t * 256;
        float acc = 0.f;
        for (int k = 0; k < 256; k++)
            acc = fmaf(__ldg(&xr[k]), __ldg(&gw1[(size_t)k * 256 + tid]), acc);
        hS[tid] = fmaxf(acc + __ldg(&gb1[tid]), 0.f);
        __syncthreads();
        int wid = tid >> 5, lane = tid & 31;
        float s = 0.f;
        for (int j = lane; j < 256; j += 32) s += hS[j] * __ldg(&gw2[j * 8 + wid]);
#pragma unroll
        for (int o = 16; o > 0; o >>= 1) s += __shfl_xor_sync(0xffffffffu, s, o);
        if (lane == 0) lg8[wid] = s + __ldg(&gb2[wid]);
        __syncthreads();
        if (tid == 0) {
            float l[CE];
#pragma unroll
            for (int e = 0; e < CE; e++) l[e] = lg8[e];
            int i0 = 0;
#pragma unroll
            for (int e = 1; e < CE; e++) if (l[e] > l[i0]) i0 = e;
            int i1 = (i0 == 0) ? 1 : 0;
#pragma unroll
            for (int e = 0; e < CE; e++) if (e != i0 && l[e] > l[i1]) i1 = e;
            g_sel[t] = i0 | (i1 << 8);
            g_w0[t]  = 1.f / (1.f + expf(l[i1] - l[i0]));
        }
        __syncthreads();
    }
}

// ---------------------------------------------------------------------------
__global__ void route_kernel()
{
    __shared__ int cnt[CE], baseI[CE];
    int tid = threadIdx.x;
    int t = blockIdx.x * 256 + tid;
    if (tid < CE) cnt[tid] = 0;
    __syncthreads();
    int sel = g_sel[t];
    int e0 = sel & 255, e1 = sel >> 8;
    float w0 = g_w0[t];
    int p0 = atomicAdd(&cnt[e0], 1);
    int p1 = atomicAdd(&cnt[e1], 1);
    __syncthreads();
    if (tid < CE) baseI[tid] = atomicAdd(&g_counts[tid], cnt[tid]);
    __syncthreads();
    int q0 = e0 * CB + baseI[e0] + p0;
    g_rtok[q0] = t; g_rw[q0] = w0;        g_rdst[q0] = 2 * t;
    int q1 = e1 * CB + baseI[e1] + p1;
    g_rtok[q1] = t; g_rw[q1] = 1.f - w0;  g_rdst[q1] = 2 * t + 1;
}

// ---------------------------------------------------------------------------
// Expert kernel: fused 3-layer MLP on routed 128-token tiles; 2-term GEMMs
// (A single fp16 plane, B exact via hi/lo); LN in registers; rows to g_eout.
// ---------------------------------------------------------------------------
__global__ void __launch_bounds__(NT, 1)
expert_kernel(const float* __restrict__ x,
              const float* __restrict__ b1, const float* __restrict__ g1,
              const float* __restrict__ be1,
              const float* __restrict__ b2, const float* __restrict__ g2,
              const float* __restrict__ be2,
              const float* __restrict__ b3)
{
    int e = blockIdx.y;
    int count = g_counts[e];
    int t0 = blockIdx.x * BM;
    if (t0 >= count) return;
    int mrows = min(BM, count - t0);

    extern __shared__ char smraw[];
    __half* Ah = (__half*)smraw;
    uint4*  Bs = (uint4*)(smraw + A1_BYTES);

    __shared__ int   tokS[BM];
    __shared__ float wS[BM];
    __shared__ int   dstS[BM];
    __shared__ float biasS[256], gamS[256], betS[256];
    __shared__ float redS[4][BM][2];
    __shared__ float mrS[BM][2];

    int tid  = threadIdx.x;
    int wid  = tid >> 5;
    int lane = tid & 31;
    int wm = wid >> 2, wn = wid & 3;
    int g = lane >> 2, tg = lane & 3;

    if (tid < BM) {
        bool v = tid < mrows;
        int q = e * CB + t0 + tid;
        tokS[tid] = v ? g_rtok[q] : 0;
        wS[tid]   = v ? g_rw[q]   : 0.f;
        dstS[tid] = v ? g_rdst[q] : 0;
    }
    __syncthreads();

    // A = gathered x rows, fp16 (hi only)
    const float4* x4 = reinterpret_cast<const float4*>(x);
    for (int i = tid; i < BM * 64; i += NT) {
        int rr = i >> 6, c4 = i & 63;
        float4 v = __ldg(&x4[(size_t)tokS[rr] * 64 + c4]);
        uint2 hh;
        hh.x = packh(__float2half_rn(v.x), __float2half_rn(v.y));
        hh.y = packh(__float2half_rn(v.z), __float2half_rn(v.w));
        *reinterpret_cast<uint2*>(Ah + rr * APH + c4 * 4) = hh;
    }

    float c[2][8][4];

    for (int l = 0; l < 3; l++) {
        if (tid < 256) {
            biasS[tid] = (l == 0 ? b1 : (l == 1 ? b2 : b3))[e * 256 + tid];
            if (l < 2) {
                gamS[tid] = (l == 0 ? g1 : g2)[e * 256 + tid];
                betS[tid] = (l == 0 ? be1 : be2)[e * 256 + tid];
            }
        }
        __syncthreads();

        gemm_core(g_wpack + (size_t)(1 + e * 3 + l) * SLABQ, Ah, Bs,
                  c, wm, wn, lane, tid);

        if (l < 2) {
            float s1[2][2] = {{0.f, 0.f}, {0.f, 0.f}};
            float s2[2][2] = {{0.f, 0.f}, {0.f, 0.f}};
#pragma unroll
            for (int m = 0; m < 2; m++)
#pragma unroll
                for (int t = 0; t < 8; t++) {
                    int colb = wn * 64 + t * 8 + tg * 2;
#pragma unroll
                    for (int h = 0; h < 2; h++)
#pragma unroll
                        for (int q = 0; q < 2; q++) {
                            float v = c[m][t][h * 2 + q] + biasS[colb + q];
                            c[m][t][h * 2 + q] = v;
                            s1[m][h] += v; s2[m][h] += v * v;
                        }
                }
#pragma unroll
            for (int off = 1; off <= 2; off <<= 1)
#pragma unroll
                for (int m = 0; m < 2; m++)
#pragma unroll
                    for (int h = 0; h < 2; h++) {
                        s1[m][h] += __shfl_xor_sync(0xffffffffu, s1[m][h], off);
                        s2[m][h] += __shfl_xor_sync(0xffffffffu, s2[m][h], off);
                    }
            if (tg == 0) {
#pragma unroll
                for (int m = 0; m < 2; m++)
#pragma unroll
                    for (int h = 0; h < 2; h++) {
                        int row = wm * 32 + m * 16 + g + h * 8;
                        redS[wn][row][0] = s1[m][h];
                        redS[wn][row][1] = s2[m][h];
                    }
            }
            __syncthreads();
            if (tid < BM) {
                float a = redS[0][tid][0] + redS[1][tid][0] + redS[2][tid][0] + redS[3][tid][0];
                float b = redS[0][tid][1] + redS[1][tid][1] + redS[2][tid][1] + redS[3][tid][1];
                float mean = a * (1.f / 256.f);
                float var  = b * (1.f / 256.f) - mean * mean;
                mrS[tid][0] = mean;
                mrS[tid][1] = rsqrtf(var + 1e-5f);
            }
            __syncthreads();
            // normalize + relu + fp16 round -> Ah (next layer A)
#pragma unroll
            for (int m = 0; m < 2; m++)
#pragma unroll
                for (int h = 0; h < 2; h++) {
                    int row = wm * 32 + m * 16 + g + h * 8;
                    float mean = mrS[row][0], rs = mrS[row][1];
#pragma unroll
                    for (int t = 0; t < 8; t++) {
                        int colb = wn * 64 + t * 8 + tg * 2;
                        float h0 = fmaxf((c[m][t][h * 2 + 0] - mean) * rs * gamS[colb]
                                         + betS[colb], 0.f);
                        float h1 = fmaxf((c[m][t][h * 2 + 1] - mean) * rs * gamS[colb + 1]
                                         + betS[colb + 1], 0.f);
                        *reinterpret_cast<uint32_t*>(Ah + row * APH + colb) =
                            packh(__float2half_rn(h0), __float2half_rn(h1));
                    }
                }
            __syncthreads();
        }
    }

    // final: +b3, gate weight, store rows to g_eout[dst]
#pragma unroll
    for (int m = 0; m < 2; m++)
#pragma unroll
        for (int h = 0; h < 2; h++) {
            int row = wm * 32 + m * 16 + g + h * 8;
            if (row < mrows) {
                float wgt = wS[row];
                float* orow = g_eout + (size_t)dstS[row] * 256;
#pragma unroll
                for (int t = 0; t < 8; t++) {
                    int colb = wn * 64 + t * 8 + tg * 2;
                    float2 v = make_float2(
                        wgt * (c[m][t][h * 2 + 0] + biasS[colb]),
                        wgt * (c[m][t][h * 2 + 1] + biasS[colb + 1]));
                    *reinterpret_cast<float2*>(orow + colb) = v;
                }
            }
        }
}

// ---------------------------------------------------------------------------
__global__ void combine_kernel(float* __restrict__ out)
{
    int i = blockIdx.x * blockDim.x + threadIdx.x;   // CB*64 float4s
    if (i >= CB * 64) return;
    int t = i >> 6, c4 = i & 63;
    const float4* e4 = reinterpret_cast<const float4*>(g_eout);
    float4 a = e4[(size_t)(2 * t) * 64 + c4];
    float4 b = e4[(size_t)(2 * t + 1) * 64 + c4];
    reinterpret_cast<float4*>(out)[i] =
        make_float4(a.x + b.x, a.y + b.y, a.z + b.z, a.w + b.w);
}

// ---------------------------------------------------------------------------
extern "C" void kernel_launch(void* const* d_in, const int* in_sizes, int n_in,
                              void* d_out, int out_size)
{
    const float* x   = (const float*)d_in[0];
    const float* gw1 = (const float*)d_in[1];
    const float* gb1 = (const float*)d_in[2];
    const float* gw2 = (const float*)d_in[3];
    const float* gb2 = (const float*)d_in[4];
    const float* w1  = (const float*)d_in[5];
    const float* b1  = (const float*)d_in[6];
    const float* g1  = (const float*)d_in[7];
    const float* be1 = (const float*)d_in[8];
    const float* w2  = (const float*)d_in[9];
    const float* b2  = (const float*)d_in[10];
    const float* g2  = (const float*)d_in[11];
    const float* be2 = (const float*)d_in[12];
    const float* w3  = (const float*)d_in[13];
    const float* b3  = (const float*)d_in[14];
    float* out = (float*)d_out;

    cudaFuncSetAttribute(gating_kernel,
                         cudaFuncAttributeMaxDynamicSharedMemorySize, SMEM_GAT);
    cudaFuncSetAttribute(expert_kernel,
                         cudaFuncAttributeMaxDynamicSharedMemorySize, SMEM_EXP);

    prep_kernel<<<dim3(64, 25), 256>>>(gw1, w1, w2, w3);

    gating_kernel<<<CB / BM, NT, SMEM_GAT>>>(x, gb1, gw2, gb2);

    fixup_kernel<<<64, 256>>>(x, gw1, gb1, gw2, gb2);

    route_kernel<<<CB / 256, 256>>>();

    dim3 egrid(CB / BM, CE);
    expert_kernel<<<egrid, NT, SMEM_EXP>>>(x, b1, g1, be1, b2, g2, be2, b3);

    combine_kernel<<<(CB * 64 + 255) / 256, 256>>>(out);
}

// round 10
// speedup vs baseline: 2.9032x; 1.0772x over previous
#include <cuda_runtime.h>
#include <cuda_fp16.h>
#include <cstdint>
#include <math.h>

#define CB 32768
#define CE 8
constexpr int NT   = 512;     // threads per block (16 warps)
constexpr int BM   = 128;     // token rows per tile
constexpr int APH  = 264;     // A row stride in fp16 units (conflict-free pad)
constexpr int SLABQ = 16384;  // uint4 per packed 256x256 slab
constexpr int CHQ   = 4096;   // uint4 per K=64 chunk (64KB)
constexpr int NBUF  = 2;      // B buffers

// dynamic smem layouts (bytes)
constexpr int B_BYTES   = NBUF * CHQ * 16;          // 131072
constexpr int A1_BYTES  = BM * APH * 2;             // 67584  (Ah only)
constexpr int SMEM_EXP  = A1_BYTES + B_BYTES;       // 198656
constexpr int SMEM_GAT  = SMEM_EXP
                        + 2048 * 4 + 256 * 4 + 4 * BM * 8 * 4;   // 224256

// ---------------------------------------------------------------------------
// Device scratch (static, graph-capturable)
// ---------------------------------------------------------------------------
__device__ int   g_counts[CE];
__device__ int   g_nfix;
__device__ int   g_fixlist[CB];
__device__ int   g_sel[CB];            // i0 | (i1<<8)
__device__ float g_w0[CB];
__device__ int   g_rtok[CE * CB];
__device__ float g_rw[CE * CB];
__device__ uint4 g_wpack[25 * SLABQ];  // fragment-packed fp16 hi/lo weights

// ---------------------------------------------------------------------------
__device__ __forceinline__ unsigned packh(__half a, __half b) {
    return (unsigned)__half_as_ushort(a) | ((unsigned)__half_as_ushort(b) << 16);
}

__device__ __forceinline__ void mma_f16(float (&c)[4], const uint32_t (&a)[4],
                                        uint32_t b0, uint32_t b1) {
    asm volatile(
        "mma.sync.aligned.m16n8k16.row.col.f32.f16.f16.f32 "
        "{%0,%1,%2,%3}, {%4,%5,%6,%7}, {%8,%9}, {%0,%1,%2,%3};"
        : "+f"(c[0]), "+f"(c[1]), "+f"(c[2]), "+f"(c[3])
        : "r"(a[0]), "r"(a[1]), "r"(a[2]), "r"(a[3]), "r"(b0), "r"(b1));
}

// A fragment via ldmatrix.x4: lane-quads 0..3 provide the four 8x8 matrices
// [rows0-7,k0-7], [rows8-15,k0-7], [rows0-7,k8-15], [rows8-15,k8-15]
// matching mma.m16n8k16 a0..a3 ordering exactly.
__device__ __forceinline__ void ldmA(uint32_t (&a)[4], const __half* p) {
    uint32_t addr = (uint32_t)__cvta_generic_to_shared(p);
    asm volatile("ldmatrix.sync.aligned.m8n8.x4.shared.b16 {%0,%1,%2,%3}, [%4];"
                 : "=r"(a[0]), "=r"(a[1]), "=r"(a[2]), "=r"(a[3]) : "r"(addr));
}

// Stage one K=64 chunk (4096 uint4 = 64KB) into bs.
__device__ __forceinline__ void prefetch_chunk(const uint4* __restrict__ Wp, int cc,
                                               uint4* bs, int tid) {
    unsigned dst = (unsigned)__cvta_generic_to_shared(bs);
    const uint4* src = Wp + cc * CHQ;
#pragma unroll
    for (int i = 0; i < 8; i++) {
        int idx = i * NT + tid;
        asm volatile("cp.async.cg.shared.global [%0], [%1], 16;"
                     :: "r"(dst + idx * 16), "l"(src + idx));
    }
    asm volatile("cp.async.commit_group;");
}

// ---------------------------------------------------------------------------
// 128x256x256 GEMM, m16n8k16, 2-term fp16 split: ah*bh + ah*bl = ah*(b exact).
// Only error source: rounding A to fp16 (validated: ~1.2e-4 per GEMM).
// B fragments pre-packed: uint4 {bh0,bh1,bl0,bl1} at index st*1024 + nt*32 + lane,
//   k0 = st*16 + (lane&3)*2 (+1,+8,+9), n = nt*8 + (lane>>2).
// A fragments loaded with ldmatrix.x4 (lane address: row = (quad&1)*8 + lane&7,
// k offset = (quad>>1)*8); conflict-free with APH=264.
// Buffer protocol per chunk cc: wait_group 0 -> barrier -> prefetch cc+1 ->
// consume cc (4 k16-steps) -> barrier. NBUF=2, overlapped, race-free.
// ---------------------------------------------------------------------------
__device__ __forceinline__ void gemm_core(const uint4* __restrict__ Wp,
                                          const __half* __restrict__ Ah,
                                          uint4* Bs, float (&c)[2][8][4],
                                          int wm, int wn, int lane, int tid)
{
#pragma unroll
    for (int m = 0; m < 2; m++)
#pragma unroll
        for (int t = 0; t < 8; t++)
#pragma unroll
            for (int k = 0; k < 4; k++) c[m][t][k] = 0.f;

    // per-lane ldmatrix base address within the warp's 32-row A stripe
    int quad = lane >> 3;
    const __half* aBase = Ah + (wm * 32 + (quad & 1) * 8 + (lane & 7)) * APH
                        + (quad >> 1) * 8;

    prefetch_chunk(Wp, 0, Bs, tid);

    for (int cc = 0; cc < 4; cc++) {
        asm volatile("cp.async.wait_group 0;" ::: "memory");
        __syncthreads();
        if (cc < 3)
            prefetch_chunk(Wp, cc + 1, Bs + ((cc + 1) & 1) * CHQ, tid);

        const uint4* bb = Bs + (cc & 1) * CHQ;
#pragma unroll
        for (int s = 0; s < 4; s++) {
            int kb = cc * 64 + s * 16;
            uint32_t ah_[2][4];
#pragma unroll
            for (int m = 0; m < 2; m++)
                ldmA(ah_[m], aBase + m * 16 * APH + kb);
            const uint4* bp = bb + s * 1024 + wn * 256 + lane;
#pragma unroll
            for (int t = 0; t < 8; t++) {
                uint4 bv = bp[t * 32];
#pragma unroll
                for (int m = 0; m < 2; m++) {
                    mma_f16(c[m][t], ah_[m], bv.x, bv.y);   // ah*bh
                    mma_f16(c[m][t], ah_[m], bv.z, bv.w);   // ah*bl
                }
            }
        }
        __syncthreads();   // all reads of buf cc done before it is refilled
    }
}

// ---------------------------------------------------------------------------
// prep: zero counters + output; pack 25 slabs into fp16 hi/lo fragment uint4s.
// ---------------------------------------------------------------------------
__global__ void prep_kernel(const float* __restrict__ gw1,
                            const float* __restrict__ w1,
                            const float* __restrict__ w2,
                            const float* __restrict__ w3,
                            float* __restrict__ out)
{
    int tid = threadIdx.x;
    if (blockIdx.x == 0 && blockIdx.y == 0) {
        if (tid < CE) g_counts[tid] = 0;
        if (tid == CE) g_nfix = 0;
    }
    // zero the output (CB*256 floats = 2097152 float4s) across all 1600 blocks
    {
        int lin = (blockIdx.y * 64 + blockIdx.x) * 256 + tid;   // 0..409599
        float4 z = make_float4(0.f, 0.f, 0.f, 0.f);
        for (int i = lin; i < CB * 64; i += 1600 * 256)
            reinterpret_cast<float4*>(out)[i] = z;
    }

    int slab = blockIdx.y;
    const float* src;
    if (slab == 0) src = gw1;
    else {
        int e = (slab - 1) / 3, l = (slab - 1) % 3;
        src = (l == 0 ? w1 : (l == 1 ? w2 : w3)) + (size_t)e * 65536;
    }
    int idx  = blockIdx.x * 256 + tid;     // 0..16383
    int lane = idx & 31;
    int nt   = (idx >> 5) & 31;
    int st   = idx >> 10;                  // 0..15
    int k0 = st * 16 + (lane & 3) * 2;
    int n  = nt * 8 + (lane >> 2);

    float v00 = src[(size_t)k0 * 256 + n];
    float v01 = src[(size_t)(k0 + 1) * 256 + n];
    float v10 = src[(size_t)(k0 + 8) * 256 + n];
    float v11 = src[(size_t)(k0 + 9) * 256 + n];
    __half h00 = __float2half_rn(v00), h01 = __float2half_rn(v01);
    __half h10 = __float2half_rn(v10), h11 = __float2half_rn(v11);
    __half l00 = __float2half_rn(v00 - __half2float(h00));
    __half l01 = __float2half_rn(v01 - __half2float(h01));
    __half l10 = __float2half_rn(v10 - __half2float(h10));
    __half l11 = __float2half_rn(v11 - __half2float(h11));
    uint4 o;
    o.x = packh(h00, h01); o.y = packh(h10, h11);
    o.z = packh(l00, l01); o.w = packh(l10, l11);
    g_wpack[(size_t)slab * SLABQ + idx] = o;
}

// ---------------------------------------------------------------------------
// Gating: 2-term fp16-split GEMM1 (B exact; logit err ~5e-6 << 1e-4 margin)
// -> relu(+gb1) -> fp32 logits -> top-2; near-ties flagged for exact fixup.
// ---------------------------------------------------------------------------
__global__ void __launch_bounds__(NT, 1)
gating_kernel(const float* __restrict__ x,
              const float* __restrict__ gb1,
              const float* __restrict__ gw2,
              const float* __restrict__ gb2)
{
    extern __shared__ char smraw[];
    __half* Ah   = (__half*)smraw;
    uint4*  Bs   = (uint4*)(smraw + A1_BYTES);
    float*  gw2s = (float*)(smraw + SMEM_EXP);            // 2048
    float*  gb1s = gw2s + 2048;                           // 256
    float (*lgS)[BM][8] = (float (*)[BM][8])(gb1s + 256); // [4][BM][8]

    int tid  = threadIdx.x;
    int wid  = tid >> 5;
    int lane = tid & 31;
    int wm = wid >> 2, wn = wid & 3;
    int g = lane >> 2, tg = lane & 3;
    int t0 = blockIdx.x * BM;

    for (int i = tid; i < 2048; i += NT) gw2s[i] = gw2[i];
    if (tid < 256) gb1s[tid] = gb1[tid];

    // A = x rows, fp16 (hi only)
    const float4* x4 = reinterpret_cast<const float4*>(x);
    for (int i = tid; i < BM * 64; i += NT) {
        int rr = i >> 6, c4 = i & 63;
        float4 v = __ldg(&x4[(size_t)(t0 + rr) * 64 + c4]);
        uint2 hh;
        hh.x = packh(__float2half_rn(v.x), __float2half_rn(v.y));
        hh.y = packh(__float2half_rn(v.z), __float2half_rn(v.w));
        *reinterpret_cast<uint2*>(Ah + rr * APH + c4 * 4) = hh;
    }
    __syncthreads();

    float c[2][8][4];
    gemm_core(g_wpack, Ah, Bs, c, wm, wn, lane, tid);

    // logits partials (fp32)
    float lg[2][2][8];
#pragma unroll
    for (int m = 0; m < 2; m++)
#pragma unroll
        for (int h = 0; h < 2; h++)
#pragma unroll
            for (int e = 0; e < 8; e++) lg[m][h][e] = 0.f;

#pragma unroll
    for (int m = 0; m < 2; m++)
#pragma unroll
        for (int t = 0; t < 8; t++) {
            int colb = wn * 64 + t * 8 + tg * 2;
#pragma unroll
            for (int h = 0; h < 2; h++)
#pragma unroll
                for (int q = 0; q < 2; q++) {
                    int col = colb + q;
                    float hv = fmaxf(c[m][t][h * 2 + q] + gb1s[col], 0.f);
                    const float4* gp = reinterpret_cast<const float4*>(gw2s + col * 8);
                    float4 p0 = gp[0], p1 = gp[1];
                    lg[m][h][0] += hv * p0.x; lg[m][h][1] += hv * p0.y;
                    lg[m][h][2] += hv * p0.z; lg[m][h][3] += hv * p0.w;
                    lg[m][h][4] += hv * p1.x; lg[m][h][5] += hv * p1.y;
                    lg[m][h][6] += hv * p1.z; lg[m][h][7] += hv * p1.w;
                }
        }
#pragma unroll
    for (int off = 1; off <= 2; off <<= 1)
#pragma unroll
        for (int m = 0; m < 2; m++)
#pragma unroll
            for (int h = 0; h < 2; h++)
#pragma unroll
                for (int e = 0; e < 8; e++)
                    lg[m][h][e] += __shfl_xor_sync(0xffffffffu, lg[m][h][e], off);
    if (tg == 0) {
#pragma unroll
        for (int m = 0; m < 2; m++)
#pragma unroll
            for (int h = 0; h < 2; h++) {
                int row = wm * 32 + m * 16 + g + h * 8;
#pragma unroll
                for (int e = 0; e < 8; e++) lgS[wn][row][e] = lg[m][h][e];
            }
    }
    __syncthreads();

    if (tid < BM) {
        float l[CE];
#pragma unroll
        for (int e = 0; e < CE; e++)
            l[e] = lgS[0][tid][e] + lgS[1][tid][e] + lgS[2][tid][e] + lgS[3][tid][e]
                 + __ldg(&gb2[e]);
        int i0 = 0;
#pragma unroll
        for (int e = 1; e < CE; e++) if (l[e] > l[i0]) i0 = e;
        int i1 = (i0 == 0) ? 1 : 0;
#pragma unroll
        for (int e = 0; e < CE; e++) if (e != i0 && l[e] > l[i1]) i1 = e;
        float l2v = -1e30f;
#pragma unroll
        for (int e = 0; e < CE; e++)
            if (e != i0 && e != i1 && l[e] > l2v) l2v = l[e];
        float w0 = 1.f / (1.f + expf(l[i1] - l[i0]));
        int tok = t0 + tid;
        g_sel[tok] = i0 | (i1 << 8);
        g_w0[tok]  = w0;
        if (l[i1] - l2v < 1e-4f) {
            int p = atomicAdd(&g_nfix, 1);
            g_fixlist[p] = tok;
        }
    }
}

// ---------------------------------------------------------------------------
// Exact-fp32 gating recompute for flagged near-tie tokens.
// ---------------------------------------------------------------------------
__global__ void fixup_kernel(const float* __restrict__ x,
                             const float* __restrict__ gw1,
                             const float* __restrict__ gb1,
                             const float* __restrict__ gw2,
                             const float* __restrict__ gb2)
{
    __shared__ float hS[256];
    __shared__ float lg8[CE];
    int nf = g_nfix;
    int tid = threadIdx.x;
    for (int i = blockIdx.x; i < nf; i += gridDim.x) {
        int t = g_fixlist[i];
        const float* xr = x + (size_t)t * 256;
        float acc = 0.f;
        for (int k = 0; k < 256; k++)
            acc = fmaf(__ldg(&xr[k]), __ldg(&gw1[(size_t)k * 256 + tid]), acc);
        hS[tid] = fmaxf(acc + __ldg(&gb1[tid]), 0.f);
        __syncthreads();
        int wid = tid >> 5, lane = tid & 31;
        float s = 0.f;
        for (int j = lane; j < 256; j += 32) s += hS[j] * __ldg(&gw2[j * 8 + wid]);
#pragma unroll
        for (int o = 16; o > 0; o >>= 1) s += __shfl_xor_sync(0xffffffffu, s, o);
        if (lane == 0) lg8[wid] = s + __ldg(&gb2[wid]);
        __syncthreads();
        if (tid == 0) {
            float l[CE];
#pragma unroll
            for (int e = 0; e < CE; e++) l[e] = lg8[e];
            int i0 = 0;
#pragma unroll
            for (int e = 1; e < CE; e++) if (l[e] > l[i0]) i0 = e;
            int i1 = (i0 == 0) ? 1 : 0;
#pragma unroll
            for (int e = 0; e < CE; e++) if (e != i0 && l[e] > l[i1]) i1 = e;
            g_sel[t] = i0 | (i1 << 8);
            g_w0[t]  = 1.f / (1.f + expf(l[i1] - l[i0]));
        }
        __syncthreads();
    }
}

// ---------------------------------------------------------------------------
__global__ void route_kernel()
{
    __shared__ int cnt[CE], baseI[CE];
    int tid = threadIdx.x;
    int t = blockIdx.x * 256 + tid;
    if (tid < CE) cnt[tid] = 0;
    __syncthreads();
    int sel = g_sel[t];
    int e0 = sel & 255, e1 = sel >> 8;
    float w0 = g_w0[t];
    int p0 = atomicAdd(&cnt[e0], 1);
    int p1 = atomicAdd(&cnt[e1], 1);
    __syncthreads();
    if (tid < CE) baseI[tid] = atomicAdd(&g_counts[tid], cnt[tid]);
    __syncthreads();
    int q0 = e0 * CB + baseI[e0] + p0;
    g_rtok[q0] = t; g_rw[q0] = w0;
    int q1 = e1 * CB + baseI[e1] + p1;
    g_rtok[q1] = t; g_rw[q1] = 1.f - w0;
}

// ---------------------------------------------------------------------------
// Expert kernel: fused 3-layer MLP on routed 128-token tiles; 2-term GEMMs;
// LN in registers; weighted rows reduced directly into out (red.global.v2).
// Exactly two fp contributions per output element -> order-independent sums.
// ---------------------------------------------------------------------------
__global__ void __launch_bounds__(NT, 1)
expert_kernel(const float* __restrict__ x,
              const float* __restrict__ b1, const float* __restrict__ g1,
              const float* __restrict__ be1,
              const float* __restrict__ b2, const float* __restrict__ g2,
              const float* __restrict__ be2,
              const float* __restrict__ b3,
              float* __restrict__ out)
{
    int e = blockIdx.y;
    int count = g_counts[e];
    int t0 = blockIdx.x * BM;
    if (t0 >= count) return;
    int mrows = min(BM, count - t0);

    extern __shared__ char smraw[];
    __half* Ah = (__half*)smraw;
    uint4*  Bs = (uint4*)(smraw + A1_BYTES);

    __shared__ int   tokS[BM];
    __shared__ float wS[BM];
    __shared__ float biasS[256], gamS[256], betS[256];
    __shared__ float redS[4][BM][2];
    __shared__ float mrS[BM][2];

    int tid  = threadIdx.x;
    int wid  = tid >> 5;
    int lane = tid & 31;
    int wm = wid >> 2, wn = wid & 3;
    int g = lane >> 2, tg = lane & 3;

    if (tid < BM) {
        bool v = tid < mrows;
        int q = e * CB + t0 + tid;
        tokS[tid] = v ? g_rtok[q] : 0;
        wS[tid]   = v ? g_rw[q]   : 0.f;
    }
    __syncthreads();

    // A = gathered x rows, fp16 (hi only)
    const float4* x4 = reinterpret_cast<const float4*>(x);
    for (int i = tid; i < BM * 64; i += NT) {
        int rr = i >> 6, c4 = i & 63;
        float4 v = __ldg(&x4[(size_t)tokS[rr] * 64 + c4]);
        uint2 hh;
        hh.x = packh(__float2half_rn(v.x), __float2half_rn(v.y));
        hh.y = packh(__float2half_rn(v.z), __float2half_rn(v.w));
        *reinterpret_cast<uint2*>(Ah + rr * APH + c4 * 4) = hh;
    }

    float c[2][8][4];

    for (int l = 0; l < 3; l++) {
        if (tid < 256) {
            biasS[tid] = (l == 0 ? b1 : (l == 1 ? b2 : b3))[e * 256 + tid];
            if (l < 2) {
                gamS[tid] = (l == 0 ? g1 : g2)[e * 256 + tid];
                betS[tid] = (l == 0 ? be1 : be2)[e * 256 + tid];
            }
        }
        __syncthreads();

        gemm_core(g_wpack + (size_t)(1 + e * 3 + l) * SLABQ, Ah, Bs,
                  c, wm, wn, lane, tid);

        if (l < 2) {
            float s1[2][2] = {{0.f, 0.f}, {0.f, 0.f}};
            float s2[2][2] = {{0.f, 0.f}, {0.f, 0.f}};
#pragma unroll
            for (int m = 0; m < 2; m++)
#pragma unroll
                for (int t = 0; t < 8; t++) {
                    int colb = wn * 64 + t * 8 + tg * 2;
#pragma unroll
                    for (int h = 0; h < 2; h++)
#pragma unroll
                        for (int q = 0; q < 2; q++) {
                            float v = c[m][t][h * 2 + q] + biasS[colb + q];
                            c[m][t][h * 2 + q] = v;
                            s1[m][h] += v; s2[m][h] += v * v;
                        }
                }
#pragma unroll
            for (int off = 1; off <= 2; off <<= 1)
#pragma unroll
                for (int m = 0; m < 2; m++)
#pragma unroll
                    for (int h = 0; h < 2; h++) {
                        s1[m][h] += __shfl_xor_sync(0xffffffffu, s1[m][h], off);
                        s2[m][h] += __shfl_xor_sync(0xffffffffu, s2[m][h], off);
                    }
            if (tg == 0) {
#pragma unroll
                for (int m = 0; m < 2; m++)
#pragma unroll
                    for (int h = 0; h < 2; h++) {
                        int row = wm * 32 + m * 16 + g + h * 8;
                        redS[wn][row][0] = s1[m][h];
                        redS[wn][row][1] = s2[m][h];
                    }
            }
            __syncthreads();
            if (tid < BM) {
                float a = redS[0][tid][0] + redS[1][tid][0] + redS[2][tid][0] + redS[3][tid][0];
                float b = redS[0][tid][1] + redS[1][tid][1] + redS[2][tid][1] + redS[3][tid][1];
                float mean = a * (1.f / 256.f);
                float var  = b * (1.f / 256.f) - mean * mean;
                mrS[tid][0] = mean;
                mrS[tid][1] = rsqrtf(var + 1e-5f);
            }
            __syncthreads();
            // normalize + relu + fp16 round -> Ah (next layer A)
#pragma unroll
            for (int m = 0; m < 2; m++)
#pragma unroll
                for (int h = 0; h < 2; h++) {
                    int row = wm * 32 + m * 16 + g + h * 8;
                    float mean = mrS[row][0], rs = mrS[row][1];
#pragma unroll
                    for (int t = 0; t < 8; t++) {
                        int colb = wn * 64 + t * 8 + tg * 2;
                        float h0 = fmaxf((c[m][t][h * 2 + 0] - mean) * rs * gamS[colb]
                                         + betS[colb], 0.f);
                        float h1 = fmaxf((c[m][t][h * 2 + 1] - mean) * rs * gamS[colb + 1]
                                         + betS[colb + 1], 0.f);
                        *reinterpret_cast<uint32_t*>(Ah + row * APH + colb) =
                            packh(__float2half_rn(h0), __float2half_rn(h1));
                    }
                }
            __syncthreads();
        }
    }

    // final: +b3, gate weight, vector-reduce directly into out
#pragma unroll
    for (int m = 0; m < 2; m++)
#pragma unroll
        for (int h = 0; h < 2; h++) {
            int row = wm * 32 + m * 16 + g + h * 8;
            if (row < mrows) {
                float wgt = wS[row];
                float* orow = out + (size_t)tokS[row] * 256;
#pragma unroll
                for (int t = 0; t < 8; t++) {
                    int colb = wn * 64 + t * 8 + tg * 2;
                    float vx = wgt * (c[m][t][h * 2 + 0] + biasS[colb]);
                    float vy = wgt * (c[m][t][h * 2 + 1] + biasS[colb + 1]);
                    asm volatile("red.global.add.v2.f32 [%0], {%1, %2};"
                                 :: "l"(orow + colb), "f"(vx), "f"(vy) : "memory");
                }
            }
        }
}

// ---------------------------------------------------------------------------
extern "C" void kernel_launch(void* const* d_in, const int* in_sizes, int n_in,
                              void* d_out, int out_size)
{
    const float* x   = (const float*)d_in[0];
    const float* gw1 = (const float*)d_in[1];
    const float* gb1 = (const float*)d_in[2];
    const float* gw2 = (const float*)d_in[3];
    const float* gb2 = (const float*)d_in[4];
    const float* w1  = (const float*)d_in[5];
    const float* b1  = (const float*)d_in[6];
    const float* g1  = (const float*)d_in[7];
    const float* be1 = (const float*)d_in[8];
    const float* w2  = (const float*)d_in[9];
    const float* b2  = (const float*)d_in[10];
    const float* g2  = (const float*)d_in[11];
    const float* be2 = (const float*)d_in[12];
    const float* w3  = (const float*)d_in[13];
    const float* b3  = (const float*)d_in[14];
    float* out = (float*)d_out;

    cudaFuncSetAttribute(gating_kernel,
                         cudaFuncAttributeMaxDynamicSharedMemorySize, SMEM_GAT);
    cudaFuncSetAttribute(expert_kernel,
                         cudaFuncAttributeMaxDynamicSharedMemorySize, SMEM_EXP);

    prep_kernel<<<dim3(64, 25), 256>>>(gw1, w1, w2, w3, out);

    gating_kernel<<<CB / BM, NT, SMEM_GAT>>>(x, gb1, gw2, gb2);

    fixup_kernel<<<64, 256>>>(x, gw1, gb1, gw2, gb2);

    route_kernel<<<CB / 256, 256>>>();

    dim3 egrid(CB / BM, CE);
    expert_kernel<<<egrid, NT, SMEM_EXP>>>(x, b1, g1, be1, b2, g2, be2, b3, out);
}

// round 13
// speedup vs baseline: 3.2947x; 1.1349x over previous
#include <cuda_runtime.h>
#include <cuda_fp16.h>
#include <cstdint>
#include <math.h>

#define CB 32768
#define CE 8
constexpr int APH  = 264;     // A row stride in fp16 units (conflict-free pad)
constexpr int SLABQ = 16384;  // uint4 per packed 256x256 slab

// expert config: 2 CTAs/SM
constexpr int ENT  = 256;     // threads (8 warps)
constexpr int EBM  = 64;      // token rows per tile
constexpr int ECHQ = 2048;    // uint4 per K=32 chunk (32KB)
constexpr int ENCH = 8;       // chunks per GEMM
constexpr int ETILES = CB / EBM;   // 512 tiles per expert
// gating config: 1 CTA/SM
constexpr int GNT  = 512;
constexpr int GBM  = 128;
constexpr int GCHQ = 4096;    // K=64 chunks
constexpr int GNCH = 4;

// dynamic smem (bytes)
constexpr int EA_BYTES = EBM * APH * 2;                  // 33792
constexpr int EB_BYTES = 2 * ECHQ * 16;                  // 65536
constexpr int SMEM_EXP = EA_BYTES + EB_BYTES;            // 99328 (x2 CTA fits)
constexpr int GA_BYTES = GBM * APH * 2;                  // 67584
constexpr int GB_BYTES = 2 * GCHQ * 16;                  // 131072
constexpr int SMEM_GAT = GA_BYTES + GB_BYTES
                       + 2048 * 4 + 256 * 4 + 4 * GBM * 8 * 4;   // 224256

// ---------------------------------------------------------------------------
// Device scratch (static, graph-capturable)
// ---------------------------------------------------------------------------
__device__ int   g_counts[CE];
__device__ int   g_nfix;
__device__ int   g_fixlist[CB];
__device__ int   g_sel[CB];            // i0 | (i1<<8)
__device__ float g_w0[CB];
__device__ int   g_rtok[CE * CB];
__device__ float g_rw[CE * CB];
__device__ uint4 g_wpack[25 * SLABQ];  // fragment-packed fp16 hi/lo weights

// ---------------------------------------------------------------------------
__device__ __forceinline__ unsigned packh(__half a, __half b) {
    return (unsigned)__half_as_ushort(a) | ((unsigned)__half_as_ushort(b) << 16);
}

__device__ __forceinline__ void mma_f16(float (&c)[4], const uint32_t (&a)[4],
                                        uint32_t b0, uint32_t b1) {
    asm volatile(
        "mma.sync.aligned.m16n8k16.row.col.f32.f16.f16.f32 "
        "{%0,%1,%2,%3}, {%4,%5,%6,%7}, {%8,%9}, {%0,%1,%2,%3};"
        : "+f"(c[0]), "+f"(c[1]), "+f"(c[2]), "+f"(c[3])
        : "r"(a[0]), "r"(a[1]), "r"(a[2]), "r"(a[3]), "r"(b0), "r"(b1));
}

// A fragment via ldmatrix.x4: lane-quads 0..3 provide the four 8x8 matrices
// matching mma.m16n8k16 a0..a3 ordering exactly.
__device__ __forceinline__ void ldmA(uint32_t (&a)[4], const __half* p) {
    uint32_t addr = (uint32_t)__cvta_generic_to_shared(p);
    asm volatile("ldmatrix.sync.aligned.m8n8.x4.shared.b16 {%0,%1,%2,%3}, [%4];"
                 : "=r"(a[0]), "=r"(a[1]), "=r"(a[2]), "=r"(a[3]) : "r"(addr));
}

// Stage one chunk (TCHQ uint4) into bs. TCHQ/TNT == 8 for both configs.
template <int TNT, int TCHQ>
__device__ __forceinline__ void prefetch_chunk(const uint4* __restrict__ Wp, int cc,
                                               uint4* bs, int tid) {
    unsigned dst = (unsigned)__cvta_generic_to_shared(bs);
    const uint4* src = Wp + cc * TCHQ;
#pragma unroll
    for (int i = 0; i < TCHQ / TNT; i++) {
        int idx = i * TNT + tid;
        asm volatile("cp.async.cg.shared.global [%0], [%1], 16;"
                     :: "r"(dst + idx * 16), "l"(src + idx));
    }
    asm volatile("cp.async.commit_group;");
}

// ---------------------------------------------------------------------------
// (rows x 256 x 256) GEMM, m16n8k16, 2-term fp16 split: ah*bh + ah*bl.
// Warp (wm, wn) computes rows wm*32..+31, cols wn*64..+63.  Packed-B layout
// is keyed by GLOBAL k16-step st (uint4 idx = st*1024 + nt*32 + lane), so the
// chunk granularity (TCHQ) only changes copy batching, not the data layout.
// Per chunk: wait_group 0 -> barrier -> prefetch next -> consume -> barrier.
// ---------------------------------------------------------------------------
template <int TNT, int TCHQ, int NCH>
__device__ __forceinline__ void gemm_core(const uint4* __restrict__ Wp,
                                          const __half* __restrict__ Ah,
                                          uint4* Bs, float (&c)[2][8][4],
                                          int wm, int wn, int lane, int tid)
{
    constexpr int SPC = TCHQ / 1024;   // k16-steps per chunk
#pragma unroll
    for (int m = 0; m < 2; m++)
#pragma unroll
        for (int t = 0; t < 8; t++)
#pragma unroll
            for (int k = 0; k < 4; k++) c[m][t][k] = 0.f;

    int quad = lane >> 3;
    const __half* aBase = Ah + (wm * 32 + (quad & 1) * 8 + (lane & 7)) * APH
                        + (quad >> 1) * 8;

    prefetch_chunk<TNT, TCHQ>(Wp, 0, Bs, tid);

    for (int cc = 0; cc < NCH; cc++) {
        asm volatile("cp.async.wait_group 0;" ::: "memory");
        __syncthreads();
        if (cc < NCH - 1)
            prefetch_chunk<TNT, TCHQ>(Wp, cc + 1, Bs + ((cc + 1) & 1) * TCHQ, tid);

        const uint4* bb = Bs + (cc & 1) * TCHQ;
#pragma unroll
        for (int s = 0; s < SPC; s++) {
            int kb = (cc * SPC + s) * 16;
            uint32_t ah_[2][4];
#pragma unroll
            for (int m = 0; m < 2; m++)
                ldmA(ah_[m], aBase + m * 16 * APH + kb);
            const uint4* bp = bb + s * 1024 + wn * 256 + lane;
#pragma unroll
            for (int t = 0; t < 8; t++) {
                uint4 bv = bp[t * 32];
#pragma unroll
                for (int m = 0; m < 2; m++) {
                    mma_f16(c[m][t], ah_[m], bv.x, bv.y);   // ah*bh
                    mma_f16(c[m][t], ah_[m], bv.z, bv.w);   // ah*bl
                }
            }
        }
        __syncthreads();   // all reads of buf cc done before it is refilled
    }
}

// ---------------------------------------------------------------------------
// prep: zero counters + output; pack 25 slabs into fp16 hi/lo fragment uint4s.
// 1D grid: 1600 blocks; slab = bx>>6, xpart = bx&63.
// ---------------------------------------------------------------------------
__global__ void prep_kernel(const float* __restrict__ gw1,
                            const float* __restrict__ w1,
                            const float* __restrict__ w2,
                            const float* __restrict__ w3,
                            float* __restrict__ out)
{
    int tid = threadIdx.x;
    int bx  = blockIdx.x;
    if (bx == 0) {
        if (tid < CE) g_counts[tid] = 0;
        if (tid == CE) g_nfix = 0;
    }
    // zero output (CB*64 float4s) across all 1600 blocks
    {
        int lin = bx * 256 + tid;
        float4 z = make_float4(0.f, 0.f, 0.f, 0.f);
        for (int i = lin; i < CB * 64; i += 1600 * 256)
            reinterpret_cast<float4*>(out)[i] = z;
    }

    int slab  = bx >> 6;        // 0..24
    int xpart = bx & 63;        // 0..63
    const float* src;
    if (slab == 0) src = gw1;
    else {
        int e = (slab - 1) / 3, l = (slab - 1) % 3;
        src = (l == 0 ? w1 : (l == 1 ? w2 : w3)) + (size_t)e * 65536;
    }
    int idx  = xpart * 256 + tid;          // 0..16383
    int lane = idx & 31;
    int nt   = (idx >> 5) & 31;
    int st   = idx >> 10;                  // 0..15
    int k0 = st * 16 + (lane & 3) * 2;
    int n  = nt * 8 + (lane >> 2);

    float v00 = src[(size_t)k0 * 256 + n];
    float v01 = src[(size_t)(k0 + 1) * 256 + n];
    float v10 = src[(size_t)(k0 + 8) * 256 + n];
    float v11 = src[(size_t)(k0 + 9) * 256 + n];
    __half h00 = __float2half_rn(v00), h01 = __float2half_rn(v01);
    __half h10 = __float2half_rn(v10), h11 = __float2half_rn(v11);
    __half l00 = __float2half_rn(v00 - __half2float(h00));
    __half l01 = __float2half_rn(v01 - __half2float(h01));
    __half l10 = __float2half_rn(v10 - __half2float(h10));
    __half l11 = __float2half_rn(v11 - __half2float(h11));
    uint4 o;
    o.x = packh(h00, h01); o.y = packh(h10, h11);
    o.z = packh(l00, l01); o.w = packh(l10, l11);
    g_wpack[(size_t)slab * SLABQ + idx] = o;
}

// ---------------------------------------------------------------------------
// Gating: 2-term fp16-split GEMM1 (B exact) -> relu(+gb1) -> fp32 logits ->
// top-2; near-tie tokens flagged for exact fp32 fixup.
// ---------------------------------------------------------------------------
__global__ void __launch_bounds__(GNT, 1)
gating_kernel(const float* __restrict__ x,
              const float* __restrict__ gb1,
              const float* __restrict__ gw2,
              const float* __restrict__ gb2)
{
    extern __shared__ char smraw[];
    __half* Ah   = (__half*)smraw;
    uint4*  Bs   = (uint4*)(smraw + GA_BYTES);
    float*  gw2s = (float*)(smraw + GA_BYTES + GB_BYTES);  // 2048
    float*  gb1s = gw2s + 2048;                            // 256
    float (*lgS)[GBM][8] = (float (*)[GBM][8])(gb1s + 256);

    int tid  = threadIdx.x;
    int wid  = tid >> 5;
    int lane = tid & 31;
    int wm = wid >> 2, wn = wid & 3;
    int g = lane >> 2, tg = lane & 3;
    int t0 = blockIdx.x * GBM;

    for (int i = tid; i < 2048; i += GNT) gw2s[i] = gw2[i];
    if (tid < 256) gb1s[tid] = gb1[tid];

    // A = x rows, fp16 (hi only)
    const float4* x4 = reinterpret_cast<const float4*>(x);
    for (int i = tid; i < GBM * 64; i += GNT) {
        int rr = i >> 6, c4 = i & 63;
        float4 v = __ldg(&x4[(size_t)(t0 + rr) * 64 + c4]);
        uint2 hh;
        hh.x = packh(__float2half_rn(v.x), __float2half_rn(v.y));
        hh.y = packh(__float2half_rn(v.z), __float2half_rn(v.w));
        *reinterpret_cast<uint2*>(Ah + rr * APH + c4 * 4) = hh;
    }
    __syncthreads();

    float c[2][8][4];
    gemm_core<GNT, GCHQ, GNCH>(g_wpack, Ah, Bs, c, wm, wn, lane, tid);

    // logits partials (fp32)
    float lg[2][2][8];
#pragma unroll
    for (int m = 0; m < 2; m++)
#pragma unroll
        for (int h = 0; h < 2; h++)
#pragma unroll
            for (int e = 0; e < 8; e++) lg[m][h][e] = 0.f;

#pragma unroll
    for (int m = 0; m < 2; m++)
#pragma unroll
        for (int t = 0; t < 8; t++) {
            int colb = wn * 64 + t * 8 + tg * 2;
#pragma unroll
            for (int h = 0; h < 2; h++)
#pragma unroll
                for (int q = 0; q < 2; q++) {
                    int col = colb + q;
                    float hv = fmaxf(c[m][t][h * 2 + q] + gb1s[col], 0.f);
                    const float4* gp = reinterpret_cast<const float4*>(gw2s + col * 8);
                    float4 p0 = gp[0], p1 = gp[1];
                    lg[m][h][0] += hv * p0.x; lg[m][h][1] += hv * p0.y;
                    lg[m][h][2] += hv * p0.z; lg[m][h][3] += hv * p0.w;
                    lg[m][h][4] += hv * p1.x; lg[m][h][5] += hv * p1.y;
                    lg[m][h][6] += hv * p1.z; lg[m][h][7] += hv * p1.w;
                }
        }
#pragma unroll
    for (int off = 1; off <= 2; off <<= 1)
#pragma unroll
        for (int m = 0; m < 2; m++)
#pragma unroll
            for (int h = 0; h < 2; h++)
#pragma unroll
                for (int e = 0; e < 8; e++)
                    lg[m][h][e] += __shfl_xor_sync(0xffffffffu, lg[m][h][e], off);
    if (tg == 0) {
#pragma unroll
        for (int m = 0; m < 2; m++)
#pragma unroll
            for (int h = 0; h < 2; h++) {
                int row = wm * 32 + m * 16 + g + h * 8;
#pragma unroll
                for (int e = 0; e < 8; e++) lgS[wn][row][e] = lg[m][h][e];
            }
    }
    __syncthreads();

    if (tid < GBM) {
        float l[CE];
#pragma unroll
        for (int e = 0; e < CE; e++)
            l[e] = lgS[0][tid][e] + lgS[1][tid][e] + lgS[2][tid][e] + lgS[3][tid][e]
                 + __ldg(&gb2[e]);
        int i0 = 0;
#pragma unroll
        for (int e = 1; e < CE; e++) if (l[e] > l[i0]) i0 = e;
        int i1 = (i0 == 0) ? 1 : 0;
#pragma unroll
        for (int e = 0; e < CE; e++) if (e != i0 && l[e] > l[i1]) i1 = e;
        float l2v = -1e30f;
#pragma unroll
        for (int e = 0; e < CE; e++)
            if (e != i0 && e != i1 && l[e] > l2v) l2v = l[e];
        float w0 = 1.f / (1.f + expf(l[i1] - l[i0]));
        int tok = t0 + tid;
        g_sel[tok] = i0 | (i1 << 8);
        g_w0[tok]  = w0;
        if (l[i1] - l2v < 1e-4f) {
            int p = atomicAdd(&g_nfix, 1);
            g_fixlist[p] = tok;
        }
    }
}

// ---------------------------------------------------------------------------
// Exact-fp32 gating recompute for flagged near-tie tokens.
// ---------------------------------------------------------------------------
__global__ void fixup_kernel(const float* __restrict__ x,
                             const float* __restrict__ gw1,
                             const float* __restrict__ gb1,
                             const float* __restrict__ gw2,
                             const float* __restrict__ gb2)
{
    __shared__ float hS[256];
    __shared__ float lg8[CE];
    int nf = g_nfix;
    int tid = threadIdx.x;
    for (int i = blockIdx.x; i < nf; i += gridDim.x) {
        int t = g_fixlist[i];
        const float* xr = x + (size_t)t * 256;
        float acc = 0.f;
        for (int k = 0; k < 256; k++)
            acc = fmaf(__ldg(&xr[k]), __ldg(&gw1[(size_t)k * 256 + tid]), acc);
        hS[tid] = fmaxf(acc + __ldg(&gb1[tid]), 0.f);
        __syncthreads();
        int wid = tid >> 5, lane = tid & 31;
        float s = 0.f;
        for (int j = lane; j < 256; j += 32) s += hS[j] * __ldg(&gw2[j * 8 + wid]);
#pragma unroll
        for (int o = 16; o > 0; o >>= 1) s += __shfl_xor_sync(0xffffffffu, s, o);
        if (lane == 0) lg8[wid] = s + __ldg(&gb2[wid]);
        __syncthreads();
        if (tid == 0) {
            float l[CE];
#pragma unroll
            for (int e = 0; e < CE; e++) l[e] = lg8[e];
            int i0 = 0;
#pragma unroll
            for (int e = 1; e < CE; e++) if (l[e] > l[i0]) i0 = e;
            int i1 = (i0 == 0) ? 1 : 0;
#pragma unroll
            for (int e = 0; e < CE; e++) if (e != i0 && l[e] > l[i1]) i1 = e;
            g_sel[t] = i0 | (i1 << 8);
            g_w0[t]  = 1.f / (1.f + expf(l[i1] - l[i0]));
        }
        __syncthreads();
    }
}

// ---------------------------------------------------------------------------
__global__ void route_kernel()
{
    __shared__ int cnt[CE], baseI[CE];
    int tid = threadIdx.x;
    int t = blockIdx.x * 256 + tid;
    if (tid < CE) cnt[tid] = 0;
    __syncthreads();
    int sel = g_sel[t];
    int e0 = sel & 255, e1 = sel >> 8;
    float w0 = g_w0[t];
    int p0 = atomicAdd(&cnt[e0], 1);
    int p1 = atomicAdd(&cnt[e1], 1);
    __syncthreads();
    if (tid < CE) baseI[tid] = atomicAdd(&g_counts[tid], cnt[tid]);
    __syncthreads();
    int q0 = e0 * CB + baseI[e0] + p0;
    g_rtok[q0] = t; g_rw[q0] = w0;
    int q1 = e1 * CB + baseI[e1] + p1;
    g_rtok[q1] = t; g_rw[q1] = 1.f - w0;
}

// ---------------------------------------------------------------------------
// Expert kernel: fused 3-layer MLP on routed 64-token tiles; 2 CTAs/SM so
// one CTA's barriers/epilogues hide under the other's mma stream.
// 1D grid: block = tile + expert*ETILES.
// 2-term GEMMs; LN in registers; rows reduced into out (red.global.v2).
// ---------------------------------------------------------------------------
__global__ void __launch_bounds__(ENT, 2)
expert_kernel(const float* __restrict__ x,
              const float* __restrict__ b1, const float* __restrict__ g1,
              const float* __restrict__ be1,
              const float* __restrict__ b2, const float* __restrict__ g2,
              const float* __restrict__ be2,
              const float* __restrict__ b3,
              float* __restrict__ out)
{
    int e  = blockIdx.x >> 9;            // /ETILES
    int bt = blockIdx.x & (ETILES - 1);
    int count = g_counts[e];
    int t0 = bt * EBM;
    if (t0 >= count) return;
    int mrows = min(EBM, count - t0);

    extern __shared__ char smraw[];
    __half* Ah = (__half*)smraw;
    uint4*  Bs = (uint4*)(smraw + EA_BYTES);

    __shared__ int   tokS[EBM];
    __shared__ float wS[EBM];
    __shared__ float biasS[256], gamS[256], betS[256];
    __shared__ float redS[4][EBM][2];
    __shared__ float mrS[EBM][2];

    int tid  = threadIdx.x;
    int wid  = tid >> 5;
    int lane = tid & 31;
    int wm = wid >> 2, wn = wid & 3;
    int g = lane >> 2, tg = lane & 3;

    if (tid < EBM) {
        bool v = tid < mrows;
        int q = e * CB + t0 + tid;
        tokS[tid] = v ? g_rtok[q] : 0;
        wS[tid]   = v ? g_rw[q]   : 0.f;
    }
    __syncthreads();

    // A = gathered x rows, fp16 (hi only)
    const float4* x4 = reinterpret_cast<const float4*>(x);
    for (int i = tid; i < EBM * 64; i += ENT) {
        int rr = i >> 6, c4 = i & 63;
        float4 v = __ldg(&x4[(size_t)tokS[rr] * 64 + c4]);
        uint2 hh;
        hh.x = packh(__float2half_rn(v.x), __float2half_rn(v.y));
        hh.y = packh(__float2half_rn(v.z), __float2half_rn(v.w));
        *reinterpret_cast<uint2*>(Ah + rr * APH + c4 * 4) = hh;
    }

    float c[2][8][4];

    for (int l = 0; l < 3; l++) {
        if (tid < 256) {
            biasS[tid] = (l == 0 ? b1 : (l == 1 ? b2 : b3))[e * 256 + tid];
            if (l < 2) {
                gamS[tid] = (l == 0 ? g1 : g2)[e * 256 + tid];
                betS[tid] = (l == 0 ? be1 : be2)[e * 256 + tid];
            }
        }
        __syncthreads();

        gemm_core<ENT, ECHQ, ENCH>(g_wpack + (size_t)(1 + e * 3 + l) * SLABQ,
                                   Ah, Bs, c, wm, wn, lane, tid);

        if (l < 2) {
            float s1[2][2] = {{0.f, 0.f}, {0.f, 0.f}};
            float s2[2][2] = {{0.f, 0.f}, {0.f, 0.f}};
#pragma unroll
            for (int m = 0; m < 2; m++)
#pragma unroll
                for (int t = 0; t < 8; t++) {
                    int colb = wn * 64 + t * 8 + tg * 2;
#pragma unroll
                    for (int h = 0; h < 2; h++)
#pragma unroll
                        for (int q = 0; q < 2; q++) {
                            float v = c[m][t][h * 2 + q] + biasS[colb + q];
                            c[m][t][h * 2 + q] = v;
                            s1[m][h] += v; s2[m][h] += v * v;
                        }
                }
#pragma unroll
            for (int off = 1; off <= 2; off <<= 1)
#pragma unroll
                for (int m = 0; m < 2; m++)
#pragma unroll
                    for (int h = 0; h < 2; h++) {
                        s1[m][h] += __shfl_xor_sync(0xffffffffu, s1[m][h], off);
                        s2[m][h] += __shfl_xor_sync(0xffffffffu, s2[m][h], off);
                    }
            if (tg == 0) {
#pragma unroll
                for (int m = 0; m < 2; m++)
#pragma unroll
                    for (int h = 0; h < 2; h++) {
                        int row = wm * 32 + m * 16 + g + h * 8;
                        redS[wn][row][0] = s1[m][h];
                        redS[wn][row][1] = s2[m][h];
                    }
            }
            __syncthreads();
            if (tid < EBM) {
                float a = redS[0][tid][0] + redS[1][tid][0] + redS[2][tid][0] + redS[3][tid][0];
                float b = redS[0][tid][1] + redS[1][tid][1] + redS[2][tid][1] + redS[3][tid][1];
                float mean = a * (1.f / 256.f);
                float var  = b * (1.f / 256.f) - mean * mean;
                mrS[tid][0] = mean;
                mrS[tid][1] = rsqrtf(var + 1e-5f);
            }
            __syncthreads();
            // normalize + relu + fp16 round -> Ah (next layer A)
#pragma unroll
            for (int m = 0; m < 2; m++)
#pragma unroll
                for (int h = 0; h < 2; h++) {
                    int row = wm * 32 + m * 16 + g + h * 8;
                    float mean = mrS[row][0], rs = mrS[row][1];
#pragma unroll
                    for (int t = 0; t < 8; t++) {
                        int colb = wn * 64 + t * 8 + tg * 2;
                        float h0 = fmaxf((c[m][t][h * 2 + 0] - mean) * rs * gamS[colb]
                                         + betS[colb], 0.f);
                        float h1 = fmaxf((c[m][t][h * 2 + 1] - mean) * rs * gamS[colb + 1]
                                         + betS[colb + 1], 0.f);
                        *reinterpret_cast<uint32_t*>(Ah + row * APH + colb) =
                            packh(__float2half_rn(h0), __float2half_rn(h1));
                    }
                }
            __syncthreads();
        }
    }

    // final: +b3, gate weight, vector-reduce directly into out
#pragma unroll
    for (int m = 0; m < 2; m++)
#pragma unroll
        for (int h = 0; h < 2; h++) {
            int row = wm * 32 + m * 16 + g + h * 8;
            if (row < mrows) {
                float wgt = wS[row];
                float* orow = out + (size_t)tokS[row] * 256;
#pragma unroll
                for (int t = 0; t < 8; t++) {
                    int colb = wn * 64 + t * 8 + tg * 2;
                    float vx = wgt * (c[m][t][h * 2 + 0] + biasS[colb]);
                    float vy = wgt * (c[m][t][h * 2 + 1] + biasS[colb + 1]);
                    asm volatile("red.global.add.v2.f32 [%0], {%1, %2};"
                                 :: "l"(orow + colb), "f"(vx), "f"(vy) : "memory");
                }
            }
        }
}

// ---------------------------------------------------------------------------
extern "C" void kernel_launch(void* const* d_in, const int* in_sizes, int n_in,
                              void* d_out, int out_size)
{
    const float* x   = (const float*)d_in[0];
    const float* gw1 = (const float*)d_in[1];
    const float* gb1 = (const float*)d_in[2];
    const float* gw2 = (const float*)d_in[3];
    const float* gb2 = (const float*)d_in[4];
    const float* w1  = (const float*)d_in[5];
    const float* b1  = (const float*)d_in[6];
    const float* g1  = (const float*)d_in[7];
    const float* be1 = (const float*)d_in[8];
    const float* w2  = (const float*)d_in[9];
    const float* b2  = (const float*)d_in[10];
    const float* g2  = (const float*)d_in[11];
    const float* be2 = (const float*)d_in[12];
    const float* w3  = (const float*)d_in[13];
    const float* b3  = (const float*)d_in[14];
    float* out = (float*)d_out;

    cudaFuncSetAttribute(gating_kernel,
                         cudaFuncAttributeMaxDynamicSharedMemorySize, SMEM_GAT);
    cudaFuncSetAttribute(expert_kernel,
                         cudaFuncAttributeMaxDynamicSharedMemorySize, SMEM_EXP);

    prep_kernel<<<1600, 256>>>(gw1, w1, w2, w3, out);

    gating_kernel<<<CB / GBM, GNT, SMEM_GAT>>>(x, gb1, gw2, gb2);

    fixup_kernel<<<64, 256>>>(x, gw1, gb1, gw2, gb2);

    route_kernel<<<CB / 256, 256>>>();

    expert_kernel<<<ETILES * CE, ENT, SMEM_EXP>>>(x, b1, g1, be1,
                                                  b2, g2, be2, b3, out);
}